// round 1
// baseline (speedup 1.0000x reference)
#include <cuda_runtime.h>
#include <cstdint>

#define DD 1024
#define NB 4
#define SQ 2048
#define ROWS (NB*SQ)            /* 8192 */
#define NELEM (ROWS*DD)         /* 8388608 */

// ---------------- scratch (device globals; no allocation allowed) ----------------
__device__ float g_absmax[4];
__device__ float g_nx[NELEM];          // rmsnorm1 output (also conv input)
__device__ float g_nx2[NELEM];         // quantized nx early; rmsnorm2/quant later
__device__ float g_qkv[ROWS*3*DD];     // qkv projection
__device__ float g_attnpre[NELEM];     // attention output pre out-proj
__device__ float g_hattn[NELEM];       // attention output post out-proj
__device__ float g_xbuf[NELEM];        // x after first residual
__device__ float g_ff1[ROWS*4*DD];     // w1 out -> gated -> quantized gated
__device__ float g_ff2[ROWS*4*DD];     // w2 out

// ---------------- small kernels ----------------
__global__ void zero_absmax_kernel() {
    if (threadIdx.x < 4) g_absmax[threadIdx.x] = 0.f;
}

// rmsnorm row kernel + global absmax of output (slot)
__global__ void __launch_bounds__(256) rmsnorm_kernel(
    const float* __restrict__ x, const float* __restrict__ w,
    float* __restrict__ out, int slot)
{
    __shared__ float red[256];
    int tid = threadIdx.x;
    size_t row = blockIdx.x;
    float4 xv = ((const float4*)(x + row*DD))[tid];
    float ss = xv.x*xv.x + xv.y*xv.y + xv.z*xv.z + xv.w*xv.w;
    red[tid] = ss;
    __syncthreads();
    #pragma unroll
    for (int s = 128; s > 0; s >>= 1) {
        if (tid < s) red[tid] += red[tid + s];
        __syncthreads();
    }
    float rinv = rsqrtf(red[0] * (1.f/1024.f) + 1e-6f);
    __syncthreads();
    float4 wv = ((const float4*)w)[tid];
    float4 o;
    o.x = wv.x * (xv.x * rinv);
    o.y = wv.y * (xv.y * rinv);
    o.z = wv.z * (xv.z * rinv);
    o.w = wv.w * (xv.w * rinv);
    ((float4*)(out + row*DD))[tid] = o;
    float am = fmaxf(fmaxf(fabsf(o.x), fabsf(o.y)), fmaxf(fabsf(o.z), fabsf(o.w)));
    red[tid] = am;
    __syncthreads();
    #pragma unroll
    for (int s = 128; s > 0; s >>= 1) {
        if (tid < s) red[tid] = fmaxf(red[tid], red[tid + s]);
        __syncthreads();
    }
    if (tid == 0) atomicMax((int*)&g_absmax[slot], __float_as_int(red[0]));
}

// fake quant: clip(round(x/scale),-128,127)*scale, scale = absmax/127 + 1e-8
__global__ void __launch_bounds__(256) quant_kernel(
    const float* __restrict__ in, float* __restrict__ out, int slot, int n4)
{
    float scale = g_absmax[slot] / 127.0f + 1e-8f;
    int stride = gridDim.x * blockDim.x;
    for (int i = blockIdx.x*blockDim.x + threadIdx.x; i < n4; i += stride) {
        float4 v = ((const float4*)in)[i];
        v.x = fminf(fmaxf(rintf(v.x / scale), -128.f), 127.f) * scale;
        v.y = fminf(fmaxf(rintf(v.y / scale), -128.f), 127.f) * scale;
        v.z = fminf(fmaxf(rintf(v.z / scale), -128.f), 127.f) * scale;
        v.w = fminf(fmaxf(rintf(v.w / scale), -128.f), 127.f) * scale;
        ((float4*)out)[i] = v;
    }
}

// silu(a)*b -> a, plus global absmax into slot
__global__ void __launch_bounds__(256) gate_kernel(
    float* __restrict__ a, const float* __restrict__ bsrc, int n4, int slot)
{
    __shared__ float red[256];
    float am = 0.f;
    int stride = gridDim.x * blockDim.x;
    for (int i = blockIdx.x*blockDim.x + threadIdx.x; i < n4; i += stride) {
        float4 u = ((const float4*)a)[i];
        float4 v = ((const float4*)bsrc)[i];
        float4 g;
        g.x = u.x / (1.f + __expf(-u.x)) * v.x;
        g.y = u.y / (1.f + __expf(-u.y)) * v.y;
        g.z = u.z / (1.f + __expf(-u.z)) * v.z;
        g.w = u.w / (1.f + __expf(-u.w)) * v.w;
        ((float4*)a)[i] = g;
        am = fmaxf(am, fmaxf(fmaxf(fabsf(g.x), fabsf(g.y)), fmaxf(fabsf(g.z), fabsf(g.w))));
    }
    red[threadIdx.x] = am;
    __syncthreads();
    #pragma unroll
    for (int s = 128; s > 0; s >>= 1) {
        if (threadIdx.x < s) red[threadIdx.x] = fmaxf(red[threadIdx.x], red[threadIdx.x + s]);
        __syncthreads();
    }
    if (threadIdx.x == 0) atomicMax((int*)&g_absmax[slot], __float_as_int(red[0]));
}

// depthwise conv5 along seq (on nx) + residual combine:
// xout = x + hrec + hattn + conv(nx)
__global__ void __launch_bounds__(256) conv_combine_kernel(
    const float* __restrict__ x, const float* __restrict__ hrec,
    const float* __restrict__ hattn, const float* __restrict__ nx,
    const float* __restrict__ conv_w, const float* __restrict__ conv_b,
    float* __restrict__ xout)
{
    int bs = blockIdx.x;
    int b = bs >> 11;
    int s = bs & 2047;
    size_t rowbase = (size_t)bs * DD;
    for (int d = threadIdx.x; d < DD; d += 256) {
        float acc = conv_b[d];
        #pragma unroll
        for (int t = 0; t < 5; t++) {
            int ssi = s + t - 2;
            if (ssi >= 0 && ssi < SQ)
                acc = fmaf(nx[((size_t)b*SQ + ssi)*DD + d], conv_w[d*5 + t], acc);
        }
        size_t idx = rowbase + d;
        xout[idx] = x[idx] + hrec[idx] + hattn[idx] + acc;
    }
}

// ---------------- SGEMM: C[M,N] = A[M,K] @ W[N,K]^T + bias, epilogues ----------------
// EPI 0: +bias. EPI 1: tanh(+bias + exp(e2[n])*e1[m,n]). EPI 2: +bias + e1[m,n].
template<int EPI>
__global__ void __launch_bounds__(256) sgemm_kernel(
    const float* __restrict__ A, const float* __restrict__ W,
    const float* __restrict__ bias, float* __restrict__ C,
    int M, int N, int K,
    const float* __restrict__ e1, const float* __restrict__ e2)
{
    __shared__ float As[16][132];
    __shared__ float Bs[16][132];
    int tid = threadIdx.x;
    int tx = tid & 15;
    int ty = tid >> 4;
    int lrow = tid >> 2;
    int lcol = (tid & 3) << 2;
    size_t aoff = ((size_t)blockIdx.y*128 + lrow)*K + lcol;
    size_t boff = ((size_t)blockIdx.x*128 + lrow)*K + lcol;

    float acc[8][8];
    #pragma unroll
    for (int i = 0; i < 8; i++)
        #pragma unroll
        for (int j = 0; j < 8; j++) acc[i][j] = 0.f;

    for (int k0 = 0; k0 < K; k0 += 16) {
        #pragma unroll
        for (int l = 0; l < 2; l++) {
            float4 av = *(const float4*)(A + aoff + (size_t)l*64*K + k0);
            As[lcol+0][lrow + l*64] = av.x;
            As[lcol+1][lrow + l*64] = av.y;
            As[lcol+2][lrow + l*64] = av.z;
            As[lcol+3][lrow + l*64] = av.w;
            float4 bv = *(const float4*)(W + boff + (size_t)l*64*K + k0);
            Bs[lcol+0][lrow + l*64] = bv.x;
            Bs[lcol+1][lrow + l*64] = bv.y;
            Bs[lcol+2][lrow + l*64] = bv.z;
            Bs[lcol+3][lrow + l*64] = bv.w;
        }
        __syncthreads();
        #pragma unroll
        for (int kk = 0; kk < 16; kk++) {
            float4 a0 = *(const float4*)&As[kk][ty*4];
            float4 a1 = *(const float4*)&As[kk][64 + ty*4];
            float4 b0 = *(const float4*)&Bs[kk][tx*4];
            float4 b1 = *(const float4*)&Bs[kk][64 + tx*4];
            float ar[8] = {a0.x, a0.y, a0.z, a0.w, a1.x, a1.y, a1.z, a1.w};
            float br[8] = {b0.x, b0.y, b0.z, b0.w, b1.x, b1.y, b1.z, b1.w};
            #pragma unroll
            for (int i = 0; i < 8; i++)
                #pragma unroll
                for (int j = 0; j < 8; j++)
                    acc[i][j] = fmaf(ar[i], br[j], acc[i][j]);
        }
        __syncthreads();
    }

    #pragma unroll
    for (int i = 0; i < 8; i++) {
        int m = blockIdx.y*128 + ((i < 4) ? (ty*4 + i) : (64 + ty*4 + i - 4));
        #pragma unroll
        for (int j = 0; j < 8; j++) {
            int n = blockIdx.x*128 + ((j < 4) ? (tx*4 + j) : (64 + tx*4 + j - 4));
            float v = acc[i][j] + bias[n];
            size_t idx = (size_t)m*N + n;
            if (EPI == 1)      v = tanhf(v + expf(e2[n]) * e1[idx]);
            else if (EPI == 2) v += e1[idx];
            C[idx] = v;
        }
    }
}

// ---------------- flash attention: 16 heads, HD=64, S=2048 ----------------
// block = (q-tile of 64 rows) x head x batch; 256 threads: 64 rows x 4 col-groups
__global__ void __launch_bounds__(256) flash_attn_kernel(
    const float* __restrict__ qkv, float* __restrict__ out)
{
    extern __shared__ float sm[];
    float* Qs = sm;
    float* Ks = sm + 64*65;
    float* Vs = sm + 2*64*65;
    float* Ps = sm + 3*64*65;

    int tid = threadIdx.x;
    int q0 = blockIdx.x * 64;
    int h  = blockIdx.y;
    int b  = blockIdx.z;
    const float* base = qkv + (size_t)b*SQ*3072 + h*64;

    for (int i = tid; i < 4096; i += 256) {
        int rr = i >> 6, cc = i & 63;
        Qs[rr*65 + cc] = base[(size_t)(q0 + rr)*3072 + cc] * 0.125f;  // 1/sqrt(64)
    }

    int r  = tid >> 2;
    int cg = tid & 3;
    float m = -1e30f, l = 0.f;
    float acc[16];
    #pragma unroll
    for (int j = 0; j < 16; j++) acc[j] = 0.f;
    __syncthreads();

    for (int k0 = 0; k0 < SQ; k0 += 64) {
        for (int i = tid; i < 4096; i += 256) {
            int rr = i >> 6, cc = i & 63;
            Ks[rr*65 + cc] = base[(size_t)(k0 + rr)*3072 + 1024 + cc];
            Vs[rr*65 + cc] = base[(size_t)(k0 + rr)*3072 + 2048 + cc];
        }
        __syncthreads();

        float s[16];
        #pragma unroll
        for (int j = 0; j < 16; j++) s[j] = 0.f;
        #pragma unroll 8
        for (int kk = 0; kk < 64; kk++) {
            float qv = Qs[r*65 + kk];
            #pragma unroll
            for (int j = 0; j < 16; j++)
                s[j] = fmaf(qv, Ks[(cg*16 + j)*65 + kk], s[j]);
        }

        float mt = s[0];
        #pragma unroll
        for (int j = 1; j < 16; j++) mt = fmaxf(mt, s[j]);
        mt = fmaxf(mt, __shfl_xor_sync(0xffffffffu, mt, 1));
        mt = fmaxf(mt, __shfl_xor_sync(0xffffffffu, mt, 2));
        float m_new = fmaxf(m, mt);
        float alpha = __expf(m - m_new);
        float lsum = 0.f;
        #pragma unroll
        for (int j = 0; j < 16; j++) { s[j] = __expf(s[j] - m_new); lsum += s[j]; }
        lsum += __shfl_xor_sync(0xffffffffu, lsum, 1);
        lsum += __shfl_xor_sync(0xffffffffu, lsum, 2);
        l = l * alpha + lsum;
        m = m_new;
        #pragma unroll
        for (int j = 0; j < 16; j++) acc[j] *= alpha;
        #pragma unroll
        for (int j = 0; j < 16; j++) Ps[r*65 + cg*16 + j] = s[j];
        __syncthreads();

        #pragma unroll 4
        for (int j = 0; j < 64; j++) {
            float p = Ps[r*65 + j];
            #pragma unroll
            for (int dd = 0; dd < 16; dd++)
                acc[dd] = fmaf(p, Vs[j*65 + cg*16 + dd], acc[dd]);
        }
        __syncthreads();
    }

    float linv = 1.f / l;
    size_t obase = ((size_t)(b*SQ + q0 + r))*DD + h*64 + cg*16;
    #pragma unroll
    for (int dd = 0; dd < 16; dd++)
        out[obase + dd] = acc[dd] * linv;
}

// ---------------- launch ----------------
extern "C" void kernel_launch(void* const* d_in, const int* in_sizes, int n_in,
                              void* d_out, int out_size)
{
    const float* x         = (const float*)d_in[0];
    const float* h_prev    = (const float*)d_in[1];
    const float* norm1_w   = (const float*)d_in[2];
    const float* norm2_w   = (const float*)d_in[3];
    const float* decay     = (const float*)d_in[4];
    const float* rec_W     = (const float*)d_in[5];
    const float* rec_b     = (const float*)d_in[6];
    const float* in_proj_w = (const float*)d_in[7];
    const float* in_proj_b = (const float*)d_in[8];
    const float* out_w     = (const float*)d_in[9];
    const float* out_b     = (const float*)d_in[10];
    const float* conv_w    = (const float*)d_in[11];
    const float* conv_b    = (const float*)d_in[12];
    const float* w1_W      = (const float*)d_in[13];
    const float* w1_b      = (const float*)d_in[14];
    const float* w2_W      = (const float*)d_in[15];
    const float* w2_b      = (const float*)d_in[16];
    const float* w3_W      = (const float*)d_in[17];
    const float* w3_b      = (const float*)d_in[18];

    float* out_x    = (float*)d_out;
    float* out_hrec = out_x + NELEM;

    float *nx, *nx2, *qkv, *attnpre, *hattn, *xbuf, *ff1, *ff2;
    cudaGetSymbolAddress((void**)&nx,      g_nx);
    cudaGetSymbolAddress((void**)&nx2,     g_nx2);
    cudaGetSymbolAddress((void**)&qkv,     g_qkv);
    cudaGetSymbolAddress((void**)&attnpre, g_attnpre);
    cudaGetSymbolAddress((void**)&hattn,   g_hattn);
    cudaGetSymbolAddress((void**)&xbuf,    g_xbuf);
    cudaGetSymbolAddress((void**)&ff1,     g_ff1);
    cudaGetSymbolAddress((void**)&ff2,     g_ff2);

    // 1. reset absmax slots
    zero_absmax_kernel<<<1, 32>>>();
    // 2. nx = rmsnorm(x), absmax(nx) -> slot 0
    rmsnorm_kernel<<<ROWS, 256>>>(x, norm1_w, nx, 0);
    // 3. nx2 <- quant(nx) (scratch reuse; real nx2 written later)
    quant_kernel<<<2048, 256>>>(nx, nx2, 0, NELEM/4);
    // 4. qkv = nx @ in_proj_w^T + b
    sgemm_kernel<0><<<dim3(24, 64), 256>>>(nx, in_proj_w, in_proj_b, qkv,
                                           ROWS, 3072, 1024, nullptr, nullptr);
    // 5. h_rec = tanh(quant(nx) @ rec_W^T + rec_b + exp(decay)*h_prev) -> out
    sgemm_kernel<1><<<dim3(8, 64), 256>>>(nx2, rec_W, rec_b, out_hrec,
                                          ROWS, 1024, 1024, h_prev, decay);
    // 6. flash attention
    const int FA_SMEM = 4*64*65*4;
    cudaFuncSetAttribute(flash_attn_kernel,
                         cudaFuncAttributeMaxDynamicSharedMemorySize, FA_SMEM);
    flash_attn_kernel<<<dim3(32, 16, 4), 256, FA_SMEM>>>(qkv, attnpre);
    // 7. out projection
    sgemm_kernel<0><<<dim3(8, 64), 256>>>(attnpre, out_w, out_b, hattn,
                                          ROWS, 1024, 1024, nullptr, nullptr);
    // 8. xbuf = x + h_rec + h_attn + conv(nx)
    conv_combine_kernel<<<ROWS, 256>>>(x, out_hrec, hattn, nx, conv_w, conv_b, xbuf);
    // 9. nx2 = rmsnorm(xbuf), absmax -> slot 1; quant in place
    rmsnorm_kernel<<<ROWS, 256>>>(xbuf, norm2_w, nx2, 1);
    quant_kernel<<<2048, 256>>>(nx2, nx2, 1, NELEM/4);
    // 10. ff1 = nx2q @ w1^T + b1 ; ff2 = nx2q @ w2^T + b2
    sgemm_kernel<0><<<dim3(32, 64), 256>>>(nx2, w1_W, w1_b, ff1,
                                           ROWS, 4096, 1024, nullptr, nullptr);
    sgemm_kernel<0><<<dim3(32, 64), 256>>>(nx2, w2_W, w2_b, ff2,
                                           ROWS, 4096, 1024, nullptr, nullptr);
    // 11. ff1 = silu(ff1)*ff2, absmax -> slot 2; quant in place
    gate_kernel<<<4096, 256>>>(ff1, ff2, (ROWS*4096)/4, 2);
    quant_kernel<<<4096, 256>>>(ff1, ff1, 2, (ROWS*4096)/4);
    // 12. out_x = xbuf + ff1q @ w3^T + b3
    sgemm_kernel<2><<<dim3(8, 64), 256>>>(ff1, w3_W, w3_b, out_x,
                                          ROWS, 1024, 4096, xbuf, nullptr);
}

// round 3
// speedup vs baseline: 1.1778x; 1.1778x over previous
#include <cuda_runtime.h>
#include <cstdint>

#define DD 1024
#define NB 4
#define SQ 2048
#define ROWS (NB*SQ)            /* 8192 */
#define NELEM (ROWS*DD)         /* 8388608 */

// ---------------- scratch (device globals; no allocation allowed) ----------------
__device__ float g_absmax[4];
__device__ float g_nx[NELEM];          // rmsnorm1 output (also conv input)
__device__ float g_nx2[NELEM];         // quant codes / rmsnorm2 buffer
__device__ float g_qkv[ROWS*3*DD];     // qkv projection
__device__ float g_attnpre[NELEM];     // attention output pre out-proj
__device__ float g_hattn[NELEM];       // attention output post out-proj
__device__ float g_xbuf[NELEM];        // x after first residual
__device__ float g_ff1[ROWS*4*DD];     // w1 out -> gated -> quant codes
__device__ float g_ff2[ROWS*4*DD];     // w2 out

// ---------------- helpers ----------------
__device__ __forceinline__ uint32_t smem_u32(const void* p){
    uint32_t a;
    asm("{ .reg .u64 t; cvta.to.shared.u64 t, %1; cvt.u32.u64 %0, t; }" : "=r"(a) : "l"(p));
    return a;
}
__device__ __forceinline__ void cp16(uint32_t saddr, const void* g){
    asm volatile("cp.async.cg.shared.global [%0], [%1], 16;" :: "r"(saddr), "l"(g));
}
#define CP_COMMIT() asm volatile("cp.async.commit_group;" ::: "memory")

// TA/TB conversion: 0 = raw bits (value already tf32-exact), 1 = hi (rna), 2 = lo
template<int T> __device__ __forceinline__ uint32_t cvt_tf32(float x);
template<> __device__ __forceinline__ uint32_t cvt_tf32<0>(float x){ return __float_as_uint(x); }
template<> __device__ __forceinline__ uint32_t cvt_tf32<1>(float x){
    uint32_t h; asm("cvt.rna.tf32.f32 %0, %1;" : "=r"(h) : "f"(x)); return h;
}
template<> __device__ __forceinline__ uint32_t cvt_tf32<2>(float x){
    uint32_t h; asm("cvt.rna.tf32.f32 %0, %1;" : "=r"(h) : "f"(x));
    float lo = x - __uint_as_float(h);
    uint32_t l; asm("cvt.rna.tf32.f32 %0, %1;" : "=r"(l) : "f"(lo)); return l;
}

// ---------------- small kernels ----------------
__global__ void zero_absmax_kernel() {
    if (threadIdx.x < 4) g_absmax[threadIdx.x] = 0.f;
}

__global__ void __launch_bounds__(256) rmsnorm_kernel(
    const float* __restrict__ x, const float* __restrict__ w,
    float* __restrict__ out, int slot)
{
    __shared__ float red[256];
    int tid = threadIdx.x;
    size_t row = blockIdx.x;
    float4 xv = ((const float4*)(x + row*DD))[tid];
    float ss = xv.x*xv.x + xv.y*xv.y + xv.z*xv.z + xv.w*xv.w;
    red[tid] = ss;
    __syncthreads();
    #pragma unroll
    for (int s = 128; s > 0; s >>= 1) {
        if (tid < s) red[tid] += red[tid + s];
        __syncthreads();
    }
    float rinv = rsqrtf(red[0] * (1.f/1024.f) + 1e-6f);
    __syncthreads();
    float4 wv = ((const float4*)w)[tid];
    float4 o;
    o.x = wv.x * (xv.x * rinv);
    o.y = wv.y * (xv.y * rinv);
    o.z = wv.z * (xv.z * rinv);
    o.w = wv.w * (xv.w * rinv);
    ((float4*)(out + row*DD))[tid] = o;
    float am = fmaxf(fmaxf(fabsf(o.x), fabsf(o.y)), fmaxf(fabsf(o.z), fabsf(o.w)));
    red[tid] = am;
    __syncthreads();
    #pragma unroll
    for (int s = 128; s > 0; s >>= 1) {
        if (tid < s) red[tid] = fmaxf(red[tid], red[tid + s]);
        __syncthreads();
    }
    if (tid == 0) atomicMax((int*)&g_absmax[slot], __float_as_int(red[0]));
}

// fake quant -> integer codes (dequant scale applied in GEMM epilogue)
__global__ void __launch_bounds__(256) quant_kernel(
    const float* __restrict__ in, float* __restrict__ out, int slot, int n4)
{
    float scale = g_absmax[slot] / 127.0f + 1e-8f;
    int stride = gridDim.x * blockDim.x;
    for (int i = blockIdx.x*blockDim.x + threadIdx.x; i < n4; i += stride) {
        float4 v = ((const float4*)in)[i];
        v.x = fminf(fmaxf(rintf(v.x / scale), -128.f), 127.f);
        v.y = fminf(fmaxf(rintf(v.y / scale), -128.f), 127.f);
        v.z = fminf(fmaxf(rintf(v.z / scale), -128.f), 127.f);
        v.w = fminf(fmaxf(rintf(v.w / scale), -128.f), 127.f);
        ((float4*)out)[i] = v;
    }
}

__global__ void __launch_bounds__(256) gate_kernel(
    float* __restrict__ a, const float* __restrict__ bsrc, int n4, int slot)
{
    __shared__ float red[256];
    float am = 0.f;
    int stride = gridDim.x * blockDim.x;
    for (int i = blockIdx.x*blockDim.x + threadIdx.x; i < n4; i += stride) {
        float4 u = ((const float4*)a)[i];
        float4 v = ((const float4*)bsrc)[i];
        float4 g;
        g.x = u.x / (1.f + __expf(-u.x)) * v.x;
        g.y = u.y / (1.f + __expf(-u.y)) * v.y;
        g.z = u.z / (1.f + __expf(-u.z)) * v.z;
        g.w = u.w / (1.f + __expf(-u.w)) * v.w;
        ((float4*)a)[i] = g;
        am = fmaxf(am, fmaxf(fmaxf(fabsf(g.x), fabsf(g.y)), fmaxf(fabsf(g.z), fabsf(g.w))));
    }
    red[threadIdx.x] = am;
    __syncthreads();
    #pragma unroll
    for (int s = 128; s > 0; s >>= 1) {
        if (threadIdx.x < s) red[threadIdx.x] = fmaxf(red[threadIdx.x], red[threadIdx.x + s]);
        __syncthreads();
    }
    if (threadIdx.x == 0) atomicMax((int*)&g_absmax[slot], __float_as_int(red[0]));
}

__global__ void __launch_bounds__(256) conv_combine_kernel(
    const float* __restrict__ x, const float* __restrict__ hrec,
    const float* __restrict__ hattn, const float* __restrict__ nx,
    const float* __restrict__ conv_w, const float* __restrict__ conv_b,
    float* __restrict__ xout)
{
    int bs = blockIdx.x;
    int b = bs >> 11;
    int s = bs & 2047;
    size_t rowbase = (size_t)bs * DD;
    for (int d = threadIdx.x; d < DD; d += 256) {
        float acc = conv_b[d];
        #pragma unroll
        for (int t = 0; t < 5; t++) {
            int ssi = s + t - 2;
            if (ssi >= 0 && ssi < SQ)
                acc = fmaf(nx[((size_t)b*SQ + ssi)*DD + d], conv_w[d*5 + t], acc);
        }
        size_t idx = rowbase + d;
        xout[idx] = x[idx] + hrec[idx] + hattn[idx] + acc;
    }
}

// ================= mma.sync tf32 GEMM =================
// C[M,N] = alpha*(A' @ W'^T) + bias;  MODE 0: tf32x3 (A,W fp32)  MODE 1: DUP2 (A=int codes)
// EPI 0: v   EPI 1: tanh(v + exp(e2[n])*e1[m,n])   EPI 2: v + e1[m,n]
// Tile: 128x128, KC=16, 8 warps of 64(m)x32(n). Smem row stride 20 floats.
#define KC 16
#define SROW 20
#define SSTG (128*SROW)   /* floats per matrix per stage */

template<int TA, int TB>
__device__ __forceinline__ void do_pass(
    const float* __restrict__ As, const float* __restrict__ Bs,
    int wm, int wn, int lane, float (&d)[4][4][4])
{
    int r = lane >> 2, c = lane & 3;
    #pragma unroll
    for (int kk = 0; kk < KC; kk += 8) {
        uint32_t a[4][4], b[4][2];
        #pragma unroll
        for (int i = 0; i < 4; i++) {
            const float* base = As + (wm + i*16 + r)*SROW + kk + c;
            a[i][0] = cvt_tf32<TA>(base[0]);
            a[i][1] = cvt_tf32<TA>(base[8*SROW]);
            a[i][2] = cvt_tf32<TA>(base[4]);
            a[i][3] = cvt_tf32<TA>(base[8*SROW + 4]);
        }
        #pragma unroll
        for (int j = 0; j < 4; j++) {
            const float* base = Bs + (wn + j*8 + r)*SROW + kk + c;
            b[j][0] = cvt_tf32<TB>(base[0]);
            b[j][1] = cvt_tf32<TB>(base[4]);
        }
        #pragma unroll
        for (int i = 0; i < 4; i++)
            #pragma unroll
            for (int j = 0; j < 4; j++)
                asm volatile(
                    "mma.sync.aligned.m16n8k8.row.col.f32.tf32.tf32.f32 "
                    "{%0,%1,%2,%3},{%4,%5,%6,%7},{%8,%9},{%0,%1,%2,%3};"
                    : "+f"(d[i][j][0]), "+f"(d[i][j][1]), "+f"(d[i][j][2]), "+f"(d[i][j][3])
                    : "r"(a[i][0]), "r"(a[i][1]), "r"(a[i][2]), "r"(a[i][3]),
                      "r"(b[j][0]), "r"(b[j][1]));
    }
}

template<int MODE, int EPI>
__global__ void __launch_bounds__(256) mma_gemm(
    const float* __restrict__ A, const float* __restrict__ W,
    const float* __restrict__ bias, float* __restrict__ C,
    int M, int N, int K,
    const float* __restrict__ e1, const float* __restrict__ e2, int slot)
{
    __shared__ __align__(16) float Asm[2][SSTG];
    __shared__ __align__(16) float Bsm[2][SSTG];

    int tid = threadIdx.x;
    int wid = tid >> 5, lane = tid & 31;
    int wm = (wid & 1) * 64;
    int wn = (wid >> 1) * 32;
    int m0 = blockIdx.y * 128, n0 = blockIdx.x * 128;

    uint32_t sA = smem_u32(Asm), sB = smem_u32(Bsm);
    int lrow = tid >> 2, lc4 = (tid & 3) * 4;   // chunk mapping: 256 threads x 2 = 512 chunks

    float d[4][4][4];
    #pragma unroll
    for (int i = 0; i < 4; i++)
        #pragma unroll
        for (int j = 0; j < 4; j++)
            #pragma unroll
            for (int q = 0; q < 4; q++) d[i][j][q] = 0.f;

    const int T = K / KC;

    // prologue: stage 0, stage 1
    #pragma unroll
    for (int pt = 0; pt < 2; pt++) {
        if (pt < T) {
            int kk0 = pt * KC;
            uint32_t off = (uint32_t)(pt & 1) * SSTG * 4;
            #pragma unroll
            for (int h = 0; h < 2; h++) {
                int row = lrow + h*64;
                cp16(sA + off + (row*SROW + lc4)*4, A + (size_t)(m0 + row)*K + kk0 + lc4);
                cp16(sB + off + (row*SROW + lc4)*4, W + (size_t)(n0 + row)*K + kk0 + lc4);
            }
            CP_COMMIT();
        }
    }

    for (int t = 0; t < T; t++) {
        if (t + 1 < T) asm volatile("cp.async.wait_group 1;" ::: "memory");
        else           asm volatile("cp.async.wait_group 0;" ::: "memory");
        __syncthreads();

        const float* As = Asm[t & 1];
        const float* Bs = Bsm[t & 1];
        if (MODE == 0) {
            do_pass<1,1>(As, Bs, wm, wn, lane, d);
            do_pass<2,1>(As, Bs, wm, wn, lane, d);
            do_pass<1,2>(As, Bs, wm, wn, lane, d);
        } else {
            do_pass<0,1>(As, Bs, wm, wn, lane, d);
            do_pass<0,2>(As, Bs, wm, wn, lane, d);
        }
        __syncthreads();

        if (t + 2 < T) {
            int kk0 = (t + 2) * KC;
            uint32_t off = (uint32_t)(t & 1) * SSTG * 4;
            #pragma unroll
            for (int h = 0; h < 2; h++) {
                int row = lrow + h*64;
                cp16(sA + off + (row*SROW + lc4)*4, A + (size_t)(m0 + row)*K + kk0 + lc4);
                cp16(sB + off + (row*SROW + lc4)*4, W + (size_t)(n0 + row)*K + kk0 + lc4);
            }
            CP_COMMIT();
        }
    }

    // epilogue
    float alpha = 1.f;
    if (slot >= 0) alpha = g_absmax[slot] * (1.f/127.f) + 1e-8f;
    int r = lane >> 2, c2 = (lane & 3) * 2;

    #pragma unroll
    for (int j = 0; j < 4; j++) {
        int cc = n0 + wn + j*8 + c2;
        float b0 = bias[cc], b1 = bias[cc + 1];
        float dn0 = 0.f, dn1 = 0.f;
        if (EPI == 1) { dn0 = expf(e2[cc]); dn1 = expf(e2[cc + 1]); }
        #pragma unroll
        for (int i = 0; i < 4; i++) {
            int r0 = m0 + wm + i*16 + r;
            #pragma unroll
            for (int half = 0; half < 2; half++) {
                int rr = r0 + half*8;
                size_t idx = (size_t)rr*N + cc;
                float v0 = alpha * d[i][j][half*2 + 0] + b0;
                float v1 = alpha * d[i][j][half*2 + 1] + b1;
                if (EPI == 1) {
                    v0 = tanhf(v0 + dn0 * e1[idx]);
                    v1 = tanhf(v1 + dn1 * e1[idx + 1]);
                } else if (EPI == 2) {
                    v0 += e1[idx];
                    v1 += e1[idx + 1];
                }
                float2 o; o.x = v0; o.y = v1;
                *(float2*)(C + idx) = o;
            }
        }
    }
}

// ---------------- flash attention (SIMT, unchanged) ----------------
__global__ void __launch_bounds__(256) flash_attn_kernel(
    const float* __restrict__ qkv, float* __restrict__ out)
{
    extern __shared__ float sm[];
    float* Qs = sm;
    float* Ks = sm + 64*65;
    float* Vs = sm + 2*64*65;
    float* Ps = sm + 3*64*65;

    int tid = threadIdx.x;
    int q0 = blockIdx.x * 64;
    int h  = blockIdx.y;
    int b  = blockIdx.z;
    const float* base = qkv + (size_t)b*SQ*3072 + h*64;

    for (int i = tid; i < 4096; i += 256) {
        int rr = i >> 6, cc = i & 63;
        Qs[rr*65 + cc] = base[(size_t)(q0 + rr)*3072 + cc] * 0.125f;
    }

    int r  = tid >> 2;
    int cg = tid & 3;
    float m = -1e30f, l = 0.f;
    float acc[16];
    #pragma unroll
    for (int j = 0; j < 16; j++) acc[j] = 0.f;
    __syncthreads();

    for (int k0 = 0; k0 < SQ; k0 += 64) {
        for (int i = tid; i < 4096; i += 256) {
            int rr = i >> 6, cc = i & 63;
            Ks[rr*65 + cc] = base[(size_t)(k0 + rr)*3072 + 1024 + cc];
            Vs[rr*65 + cc] = base[(size_t)(k0 + rr)*3072 + 2048 + cc];
        }
        __syncthreads();

        float s[16];
        #pragma unroll
        for (int j = 0; j < 16; j++) s[j] = 0.f;
        #pragma unroll 8
        for (int kk = 0; kk < 64; kk++) {
            float qv = Qs[r*65 + kk];
            #pragma unroll
            for (int j = 0; j < 16; j++)
                s[j] = fmaf(qv, Ks[(cg*16 + j)*65 + kk], s[j]);
        }

        float mt = s[0];
        #pragma unroll
        for (int j = 1; j < 16; j++) mt = fmaxf(mt, s[j]);
        mt = fmaxf(mt, __shfl_xor_sync(0xffffffffu, mt, 1));
        mt = fmaxf(mt, __shfl_xor_sync(0xffffffffu, mt, 2));
        float m_new = fmaxf(m, mt);
        float alpha = __expf(m - m_new);
        float lsum = 0.f;
        #pragma unroll
        for (int j = 0; j < 16; j++) { s[j] = __expf(s[j] - m_new); lsum += s[j]; }
        lsum += __shfl_xor_sync(0xffffffffu, lsum, 1);
        lsum += __shfl_xor_sync(0xffffffffu, lsum, 2);
        l = l * alpha + lsum;
        m = m_new;
        #pragma unroll
        for (int j = 0; j < 16; j++) acc[j] *= alpha;
        #pragma unroll
        for (int j = 0; j < 16; j++) Ps[r*65 + cg*16 + j] = s[j];
        __syncthreads();

        #pragma unroll 4
        for (int j = 0; j < 64; j++) {
            float p = Ps[r*65 + j];
            #pragma unroll
            for (int dd = 0; dd < 16; dd++)
                acc[dd] = fmaf(p, Vs[j*65 + cg*16 + dd], acc[dd]);
        }
        __syncthreads();
    }

    float linv = 1.f / l;
    size_t obase = ((size_t)(b*SQ + q0 + r))*DD + h*64 + cg*16;
    #pragma unroll
    for (int dd = 0; dd < 16; dd++)
        out[obase + dd] = acc[dd] * linv;
}

// ---------------- launch ----------------
extern "C" void kernel_launch(void* const* d_in, const int* in_sizes, int n_in,
                              void* d_out, int out_size)
{
    const float* x         = (const float*)d_in[0];
    const float* h_prev    = (const float*)d_in[1];
    const float* norm1_w   = (const float*)d_in[2];
    const float* norm2_w   = (const float*)d_in[3];
    const float* decay     = (const float*)d_in[4];
    const float* rec_W     = (const float*)d_in[5];
    const float* rec_b     = (const float*)d_in[6];
    const float* in_proj_w = (const float*)d_in[7];
    const float* in_proj_b = (const float*)d_in[8];
    const float* out_w     = (const float*)d_in[9];
    const float* out_b     = (const float*)d_in[10];
    const float* conv_w    = (const float*)d_in[11];
    const float* conv_b    = (const float*)d_in[12];
    const float* w1_W      = (const float*)d_in[13];
    const float* w1_b      = (const float*)d_in[14];
    const float* w2_W      = (const float*)d_in[15];
    const float* w2_b      = (const float*)d_in[16];
    const float* w3_W      = (const float*)d_in[17];
    const float* w3_b      = (const float*)d_in[18];

    float* out_x    = (float*)d_out;
    float* out_hrec = out_x + NELEM;

    float *nx, *nx2, *qkv, *attnpre, *hattn, *xbuf, *ff1, *ff2;
    cudaGetSymbolAddress((void**)&nx,      g_nx);
    cudaGetSymbolAddress((void**)&nx2,     g_nx2);
    cudaGetSymbolAddress((void**)&qkv,     g_qkv);
    cudaGetSymbolAddress((void**)&attnpre, g_attnpre);
    cudaGetSymbolAddress((void**)&hattn,   g_hattn);
    cudaGetSymbolAddress((void**)&xbuf,    g_xbuf);
    cudaGetSymbolAddress((void**)&ff1,     g_ff1);
    cudaGetSymbolAddress((void**)&ff2,     g_ff2);

    // 1. reset absmax slots
    zero_absmax_kernel<<<1, 32>>>();
    // 2. nx = rmsnorm(x), absmax(nx) -> slot 0
    rmsnorm_kernel<<<ROWS, 256>>>(x, norm1_w, nx, 0);
    // 3. nx2 <- quant codes of nx
    quant_kernel<<<2048, 256>>>(nx, nx2, 0, NELEM/4);
    // 4. qkv = nx @ in_proj_w^T + b   (tf32x3)
    mma_gemm<0,0><<<dim3(24, 64), 256>>>(nx, in_proj_w, in_proj_b, qkv,
                                         ROWS, 3072, 1024, nullptr, nullptr, -1);
    // 5. h_rec = tanh(scale0*(codes @ rec_W^T) + rec_b + exp(decay)*h_prev)
    mma_gemm<1,1><<<dim3(8, 64), 256>>>(nx2, rec_W, rec_b, out_hrec,
                                        ROWS, 1024, 1024, h_prev, decay, 0);
    // 6. flash attention
    const int FA_SMEM = 4*64*65*4;
    cudaFuncSetAttribute(flash_attn_kernel,
                         cudaFuncAttributeMaxDynamicSharedMemorySize, FA_SMEM);
    flash_attn_kernel<<<dim3(32, 16, 4), 256, FA_SMEM>>>(qkv, attnpre);
    // 7. out projection (tf32x3)
    mma_gemm<0,0><<<dim3(8, 64), 256>>>(attnpre, out_w, out_b, hattn,
                                        ROWS, 1024, 1024, nullptr, nullptr, -1);
    // 8. xbuf = x + h_rec + h_attn + conv(nx)
    conv_combine_kernel<<<ROWS, 256>>>(x, out_hrec, hattn, nx, conv_w, conv_b, xbuf);
    // 9. nx2 = rmsnorm(xbuf), absmax -> slot 1; quant codes in place
    rmsnorm_kernel<<<ROWS, 256>>>(xbuf, norm2_w, nx2, 1);
    quant_kernel<<<2048, 256>>>(nx2, nx2, 1, NELEM/4);
    // 10. ff1 = scale1*(codes @ w1^T) + b1 ; ff2 likewise
    mma_gemm<1,0><<<dim3(32, 64), 256>>>(nx2, w1_W, w1_b, ff1,
                                         ROWS, 4096, 1024, nullptr, nullptr, 1);
    mma_gemm<1,0><<<dim3(32, 64), 256>>>(nx2, w2_W, w2_b, ff2,
                                         ROWS, 4096, 1024, nullptr, nullptr, 1);
    // 11. ff1 = silu(ff1)*ff2, absmax -> slot 2; quant codes in place
    gate_kernel<<<4096, 256>>>(ff1, ff2, (ROWS*4096)/4, 2);
    quant_kernel<<<4096, 256>>>(ff1, ff1, 2, (ROWS*4096)/4);
    // 12. out_x = xbuf + scale2*(codes @ w3^T) + b3
    mma_gemm<1,2><<<dim3(8, 64), 256>>>(ff1, w3_W, w3_b, out_x,
                                        ROWS, 1024, 4096, xbuf, nullptr, 2);
}

// round 5
// speedup vs baseline: 2.3865x; 2.0262x over previous
#include <cuda_runtime.h>
#include <cstdint>

#define DD 1024
#define NB 4
#define SQ 2048
#define ROWS (NB*SQ)            /* 8192 */
#define NELEM (ROWS*DD)         /* 8388608 */

// ---------------- scratch ----------------
__device__ float g_absmax[4];
__device__ float g_nx[NELEM];
__device__ float g_nx2[NELEM];
__device__ float g_qkv[ROWS*3*DD];
__device__ float g_attnpre[NELEM];
__device__ float g_hattn[NELEM];
__device__ float g_xbuf[NELEM];
__device__ float g_ff1[ROWS*4*DD];
__device__ float g_ff2[ROWS*4*DD];

// ---------------- helpers ----------------
__device__ __forceinline__ float tf32h(float x){
    uint32_t r; asm("cvt.rna.tf32.f32 %0, %1;" : "=r"(r) : "f"(x));
    return __uint_as_float(r);
}
// fast exp: exp(x) = 2^(x*log2e), poly on [-0.5,0.5], rel err ~2e-6
__device__ __forceinline__ float fexp(float x){
    float y = x * 1.4426950408889634f;
    y = fminf(fmaxf(y, -120.f), 120.f);
    float r = rintf(y);
    float f = y - r;
    float p = 1.f + f*(0.6931471805599453f + f*(0.2402265069591007f +
              f*(0.05550410866482158f + f*(0.009618129107628477f +
              f*0.0013333558146428443f))));
    return __int_as_float(__float_as_int(p) + (((int)r) << 23));
}
__device__ __forceinline__ void mma8(float (&d)[4], const float* a, float b0, float b1){
    asm volatile("mma.sync.aligned.m16n8k8.row.col.f32.tf32.tf32.f32 "
        "{%0,%1,%2,%3},{%4,%5,%6,%7},{%8,%9},{%0,%1,%2,%3};"
        : "+f"(d[0]),"+f"(d[1]),"+f"(d[2]),"+f"(d[3])
        : "r"(__float_as_uint(a[0])),"r"(__float_as_uint(a[1])),
          "r"(__float_as_uint(a[2])),"r"(__float_as_uint(a[3])),
          "r"(__float_as_uint(b0)),"r"(__float_as_uint(b1)));
}

// ---------------- small kernels ----------------
__global__ void zero_absmax_kernel() {
    if (threadIdx.x < 4) g_absmax[threadIdx.x] = 0.f;
}

__global__ void __launch_bounds__(256) rmsnorm_kernel(
    const float* __restrict__ x, const float* __restrict__ w,
    float* __restrict__ out, int slot)
{
    __shared__ float red[256];
    int tid = threadIdx.x;
    size_t row = blockIdx.x;
    float4 xv = ((const float4*)(x + row*DD))[tid];
    float ss = xv.x*xv.x + xv.y*xv.y + xv.z*xv.z + xv.w*xv.w;
    red[tid] = ss;
    __syncthreads();
    #pragma unroll
    for (int s = 128; s > 0; s >>= 1) {
        if (tid < s) red[tid] += red[tid + s];
        __syncthreads();
    }
    float rinv = rsqrtf(red[0] * (1.f/1024.f) + 1e-6f);
    __syncthreads();
    float4 wv = ((const float4*)w)[tid];
    float4 o;
    o.x = wv.x * (xv.x * rinv);
    o.y = wv.y * (xv.y * rinv);
    o.z = wv.z * (xv.z * rinv);
    o.w = wv.w * (xv.w * rinv);
    ((float4*)(out + row*DD))[tid] = o;
    float am = fmaxf(fmaxf(fabsf(o.x), fabsf(o.y)), fmaxf(fabsf(o.z), fabsf(o.w)));
    red[tid] = am;
    __syncthreads();
    #pragma unroll
    for (int s = 128; s > 0; s >>= 1) {
        if (tid < s) red[tid] = fmaxf(red[tid], red[tid + s]);
        __syncthreads();
    }
    if (tid == 0) atomicMax((int*)&g_absmax[slot], __float_as_int(red[0]));
}

__global__ void __launch_bounds__(256) quant_kernel(
    const float* __restrict__ in, float* __restrict__ out, int slot, int n4)
{
    float scale = g_absmax[slot] / 127.0f + 1e-8f;
    int stride = gridDim.x * blockDim.x;
    for (int i = blockIdx.x*blockDim.x + threadIdx.x; i < n4; i += stride) {
        float4 v = ((const float4*)in)[i];
        v.x = fminf(fmaxf(rintf(v.x / scale), -128.f), 127.f);
        v.y = fminf(fmaxf(rintf(v.y / scale), -128.f), 127.f);
        v.z = fminf(fmaxf(rintf(v.z / scale), -128.f), 127.f);
        v.w = fminf(fmaxf(rintf(v.w / scale), -128.f), 127.f);
        ((float4*)out)[i] = v;
    }
}

__global__ void __launch_bounds__(256) gate_kernel(
    float* __restrict__ a, const float* __restrict__ bsrc, int n4, int slot)
{
    __shared__ float red[256];
    float am = 0.f;
    int stride = gridDim.x * blockDim.x;
    for (int i = blockIdx.x*blockDim.x + threadIdx.x; i < n4; i += stride) {
        float4 u = ((const float4*)a)[i];
        float4 v = ((const float4*)bsrc)[i];
        float4 g;
        g.x = u.x / (1.f + fexp(-u.x)) * v.x;
        g.y = u.y / (1.f + fexp(-u.y)) * v.y;
        g.z = u.z / (1.f + fexp(-u.z)) * v.z;
        g.w = u.w / (1.f + fexp(-u.w)) * v.w;
        ((float4*)a)[i] = g;
        am = fmaxf(am, fmaxf(fmaxf(fabsf(g.x), fabsf(g.y)), fmaxf(fabsf(g.z), fabsf(g.w))));
    }
    red[threadIdx.x] = am;
    __syncthreads();
    #pragma unroll
    for (int s = 128; s > 0; s >>= 1) {
        if (threadIdx.x < s) red[threadIdx.x] = fmaxf(red[threadIdx.x], red[threadIdx.x + s]);
        __syncthreads();
    }
    if (threadIdx.x == 0) atomicMax((int*)&g_absmax[slot], __float_as_int(red[0]));
}

__global__ void __launch_bounds__(256) conv_combine_kernel(
    const float* __restrict__ x, const float* __restrict__ hrec,
    const float* __restrict__ hattn, const float* __restrict__ nx,
    const float* __restrict__ conv_w, const float* __restrict__ conv_b,
    float* __restrict__ xout)
{
    int bs = blockIdx.x;
    int b = bs >> 11;
    int s = bs & 2047;
    size_t rowbase = (size_t)bs * DD;
    for (int d = threadIdx.x; d < DD; d += 256) {
        float acc = conv_b[d];
        #pragma unroll
        for (int t = 0; t < 5; t++) {
            int ssi = s + t - 2;
            if (ssi >= 0 && ssi < SQ)
                acc = fmaf(nx[((size_t)b*SQ + ssi)*DD + d], conv_w[d*5 + t], acc);
        }
        size_t idx = rowbase + d;
        xout[idx] = x[idx] + hrec[idx] + hattn[idx] + acc;
    }
}

// ================= mma.sync tf32 GEMM (pre-split smem) =================
#define KC 16
#define SROW 20
#define TILEF (128*SROW)   /* 2560 floats per tile */

__device__ __forceinline__ void pass16(
    const float* __restrict__ As, const float* __restrict__ Bs,
    int wm, int wn, int lane, float (&d)[4][4][4])
{
    int g = lane >> 2, t = lane & 3;
    #pragma unroll
    for (int kk = 0; kk < KC; kk += 8) {
        float a[4][4], b[4][2];
        #pragma unroll
        for (int i = 0; i < 4; i++) {
            const float* base = As + (wm + i*16 + g)*SROW + kk + t;
            a[i][0] = base[0];
            a[i][1] = base[8*SROW];
            a[i][2] = base[4];
            a[i][3] = base[8*SROW + 4];
        }
        #pragma unroll
        for (int j = 0; j < 4; j++) {
            const float* base = Bs + (wn + j*8 + g)*SROW + kk + t;
            b[j][0] = base[0];
            b[j][1] = base[4];
        }
        #pragma unroll
        for (int i = 0; i < 4; i++)
            #pragma unroll
            for (int j = 0; j < 4; j++)
                mma8(d[i][j], a[i], b[j][0], b[j][1]);
    }
}

// MODE 0: split A & B (3 passes).  MODE 1: A raw exact codes, split B (2 passes).
// EPI 0: v.  EPI 1: tanh(v + exp(e2[n])*e1[m,n]).  EPI 2: v + e1[m,n].
template<int MODE, int EPI>
__global__ void __launch_bounds__(256) mma_gemm(
    const float* __restrict__ A, const float* __restrict__ W,
    const float* __restrict__ bias, float* __restrict__ C,
    int M, int N, int K,
    const float* __restrict__ e1, const float* __restrict__ e2, int slot)
{
    extern __shared__ float smem_f[];
    const int NT = (MODE == 0) ? 4 : 3;

    int tid = threadIdx.x;
    int wid = tid >> 5, lane = tid & 31;
    int wm = (wid & 1) * 64;
    int wn = (wid >> 1) * 32;
    int m0 = blockIdx.y * 128, n0 = blockIdx.x * 128;
    int lrow = tid >> 2, lc4 = (tid & 3) * 4;

    float d[4][4][4];
    #pragma unroll
    for (int i = 0; i < 4; i++)
        #pragma unroll
        for (int j = 0; j < 4; j++)
            #pragma unroll
            for (int q = 0; q < 4; q++) d[i][j][q] = 0.f;

    float4 av[2], wv[2];
    auto LDG = [&](int t){
        int k0 = t*KC + lc4;
        av[0] = *(const float4*)(A + (size_t)(m0 + lrow)*K + k0);
        av[1] = *(const float4*)(A + (size_t)(m0 + lrow + 64)*K + k0);
        wv[0] = *(const float4*)(W + (size_t)(n0 + lrow)*K + k0);
        wv[1] = *(const float4*)(W + (size_t)(n0 + lrow + 64)*K + k0);
    };
    auto STS = [&](int s){   // s = stage index (0/1)
        float* bufA = smem_f + (size_t)s*NT*TILEF;
        float* bufB = bufA + ((MODE == 0) ? 2 : 1)*TILEF;
        #pragma unroll
        for (int h = 0; h < 2; h++) {
            int off = (lrow + h*64)*SROW + lc4;
            if (MODE == 0) {
                float4 hi, lo;
                hi.x = tf32h(av[h].x); hi.y = tf32h(av[h].y);
                hi.z = tf32h(av[h].z); hi.w = tf32h(av[h].w);
                lo.x = tf32h(av[h].x - hi.x); lo.y = tf32h(av[h].y - hi.y);
                lo.z = tf32h(av[h].z - hi.z); lo.w = tf32h(av[h].w - hi.w);
                *(float4*)(bufA + off) = hi;
                *(float4*)(bufA + TILEF + off) = lo;
            } else {
                *(float4*)(bufA + off) = av[h];
            }
            float4 hi, lo;
            hi.x = tf32h(wv[h].x); hi.y = tf32h(wv[h].y);
            hi.z = tf32h(wv[h].z); hi.w = tf32h(wv[h].w);
            lo.x = tf32h(wv[h].x - hi.x); lo.y = tf32h(wv[h].y - hi.y);
            lo.z = tf32h(wv[h].z - hi.z); lo.w = tf32h(wv[h].w - hi.w);
            *(float4*)(bufB + off) = hi;
            *(float4*)(bufB + TILEF + off) = lo;
        }
    };

    const int T = K / KC;
    LDG(0); STS(0);
    if (T > 1) LDG(1);
    __syncthreads();

    for (int t = 0; t < T; t++) {
        const float* buf = smem_f + (size_t)(t & 1)*NT*TILEF;
        if (MODE == 0) {
            pass16(buf,         buf + 2*TILEF, wm, wn, lane, d);  // Ahi*Bhi
            pass16(buf + TILEF, buf + 2*TILEF, wm, wn, lane, d);  // Alo*Bhi
            pass16(buf,         buf + 3*TILEF, wm, wn, lane, d);  // Ahi*Blo
        } else {
            pass16(buf, buf + TILEF,   wm, wn, lane, d);          // A*Bhi
            pass16(buf, buf + 2*TILEF, wm, wn, lane, d);          // A*Blo
        }
        if (t + 1 < T) {
            STS((t + 1) & 1);                    // FIXED: stage index, not tile index
            if (t + 2 < T) LDG(t + 2);
        }
        __syncthreads();
    }

    // epilogue
    float alpha = 1.f;
    if (slot >= 0) alpha = g_absmax[slot] * (1.f/127.f) + 1e-8f;
    int r = lane >> 2, c2 = (lane & 3) * 2;

    #pragma unroll
    for (int j = 0; j < 4; j++) {
        int cc = n0 + wn + j*8 + c2;
        float b0 = bias[cc], b1 = bias[cc + 1];
        float dn0 = 0.f, dn1 = 0.f;
        if (EPI == 1) { dn0 = expf(e2[cc]); dn1 = expf(e2[cc + 1]); }
        #pragma unroll
        for (int i = 0; i < 4; i++) {
            int r0 = m0 + wm + i*16 + r;
            #pragma unroll
            for (int half = 0; half < 2; half++) {
                int rr = r0 + half*8;
                size_t idx = (size_t)rr*N + cc;
                float v0 = alpha * d[i][j][half*2 + 0] + b0;
                float v1 = alpha * d[i][j][half*2 + 1] + b1;
                if (EPI == 1) {
                    v0 = tanhf(v0 + dn0 * e1[idx]);
                    v1 = tanhf(v1 + dn1 * e1[idx + 1]);
                } else if (EPI == 2) {
                    v0 += e1[idx];
                    v1 += e1[idx + 1];
                }
                float2 o; o.x = v0; o.y = v1;
                *(float2*)(C + idx) = o;
            }
        }
    }
}

// ================= MMA flash attention (tf32 x3) =================
// block: 128 q-rows x 1 head; 8 warps x 16 rows. K-tile = 64 keys.
#define SKA 68
#define SVA 72
#define SPA 68
#define OFF_KLO 4352
#define OFF_VHI 8704
#define OFF_VLO 13312
#define OFF_PHI 17920
#define OFF_PLO 26624
#define ATTN_SMEM (35328*4)

__global__ void __launch_bounds__(256) attn_mma(
    const float* __restrict__ qkv, float* __restrict__ out)
{
    extern __shared__ float smem_f[];
    float* Khi = smem_f;
    float* Klo = smem_f + OFF_KLO;
    float* Vhi = smem_f + OFF_VHI;
    float* Vlo = smem_f + OFF_VLO;
    float* Phi = smem_f + OFF_PHI;
    float* Plo = smem_f + OFF_PLO;

    int tid = threadIdx.x, w = tid >> 5, lane = tid & 31;
    int g = lane >> 2, t = lane & 3;
    int q0 = blockIdx.x * 128, h = blockIdx.y, b = blockIdx.z;
    const float* base = qkv + (size_t)b*SQ*3072 + h*64;

    // load Q (scaled by 1/8) into Phi region, then pull fragments into regs
    for (int i = tid; i < 2048; i += 256) {
        int row = i >> 4, c4 = (i & 15) * 4;
        float4 v = *(const float4*)(base + (size_t)(q0 + row)*3072 + c4);
        v.x *= 0.125f; v.y *= 0.125f; v.z *= 0.125f; v.w *= 0.125f;
        *(float4*)(Phi + row*SPA + c4) = v;
    }
    __syncthreads();

    float qh[8][4], ql[8][4];
    {
        const float* Qw = Phi + (w*16)*SPA;
        #pragma unroll
        for (int kk = 0; kk < 8; kk++) {
            #pragma unroll
            for (int q = 0; q < 4; q++) {
                int row = (q & 1) ? (g + 8) : g;
                int col = kk*8 + t + ((q & 2) ? 4 : 0);
                float x = Qw[row*SPA + col];
                qh[kk][q] = tf32h(x);
                ql[kk][q] = tf32h(x - qh[kk][q]);
            }
        }
    }

    float o[8][4];
    #pragma unroll
    for (int j = 0; j < 8; j++)
        #pragma unroll
        for (int q = 0; q < 4; q++) o[j][q] = 0.f;
    float m0 = -1e30f, m1 = -1e30f, l0 = 0.f, l1 = 0.f;

    for (int kt = 0; kt < SQ/64; kt++) {
        __syncthreads();   // all warps done reading K/V (and Q staging first iter)
        for (int i = tid; i < 1024; i += 256) {
            int row = i >> 4, c4 = (i & 15) * 4;
            const float* gp = base + (size_t)(kt*64 + row)*3072 + 1024 + c4;
            float4 kv = *(const float4*)gp;
            float4 vv = *(const float4*)(gp + 1024);
            float4 khv, klv, vhv, vlv;
            khv.x = tf32h(kv.x); khv.y = tf32h(kv.y); khv.z = tf32h(kv.z); khv.w = tf32h(kv.w);
            klv.x = tf32h(kv.x - khv.x); klv.y = tf32h(kv.y - khv.y);
            klv.z = tf32h(kv.z - khv.z); klv.w = tf32h(kv.w - khv.w);
            vhv.x = tf32h(vv.x); vhv.y = tf32h(vv.y); vhv.z = tf32h(vv.z); vhv.w = tf32h(vv.w);
            vlv.x = tf32h(vv.x - vhv.x); vlv.y = tf32h(vv.y - vhv.y);
            vlv.z = tf32h(vv.z - vhv.z); vlv.w = tf32h(vv.w - vhv.w);
            *(float4*)(Khi + row*SKA + c4) = khv;
            *(float4*)(Klo + row*SKA + c4) = klv;
            *(float4*)(Vhi + row*SVA + c4) = vhv;
            *(float4*)(Vlo + row*SVA + c4) = vlv;
        }
        __syncthreads();

        // ---- S = Q K^T ----
        float s[8][4];
        #pragma unroll
        for (int j = 0; j < 8; j++)
            #pragma unroll
            for (int q = 0; q < 4; q++) s[j][q] = 0.f;

        #pragma unroll
        for (int j = 0; j < 8; j++) {
            #pragma unroll
            for (int kk = 0; kk < 8; kk++) {
                const float* kh = Khi + (j*8 + g)*SKA + kk*8 + t;
                const float* kl = Klo + (j*8 + g)*SKA + kk*8 + t;
                float bh0 = kh[0], bh1 = kh[4];
                float bl0 = kl[0], bl1 = kl[4];
                mma8(s[j], qh[kk], bh0, bh1);
                mma8(s[j], ql[kk], bh0, bh1);
                mma8(s[j], qh[kk], bl0, bl1);
            }
        }

        // ---- online softmax ----
        float mt0 = -1e30f, mt1 = -1e30f;
        #pragma unroll
        for (int j = 0; j < 8; j++) {
            mt0 = fmaxf(mt0, fmaxf(s[j][0], s[j][1]));
            mt1 = fmaxf(mt1, fmaxf(s[j][2], s[j][3]));
        }
        mt0 = fmaxf(mt0, __shfl_xor_sync(0xffffffffu, mt0, 1));
        mt0 = fmaxf(mt0, __shfl_xor_sync(0xffffffffu, mt0, 2));
        mt1 = fmaxf(mt1, __shfl_xor_sync(0xffffffffu, mt1, 1));
        mt1 = fmaxf(mt1, __shfl_xor_sync(0xffffffffu, mt1, 2));
        float m0n = fmaxf(m0, mt0), m1n = fmaxf(m1, mt1);
        float a0 = fexp(m0 - m0n), a1 = fexp(m1 - m1n);

        float rs0 = 0.f, rs1 = 0.f;
        float* Pwh = Phi + (w*16)*SPA;
        float* Pwl = Plo + (w*16)*SPA;
        #pragma unroll
        for (int j = 0; j < 8; j++) {
            float p0 = fexp(s[j][0] - m0n), p1 = fexp(s[j][1] - m0n);
            float p2 = fexp(s[j][2] - m1n), p3 = fexp(s[j][3] - m1n);
            rs0 += p0 + p1; rs1 += p2 + p3;
            float h0 = tf32h(p0), h1 = tf32h(p1), h2 = tf32h(p2), h3 = tf32h(p3);
            int c0 = j*8 + 2*t;
            *(float2*)(Pwh + g*SPA + c0)       = make_float2(h0, h1);
            *(float2*)(Pwh + (g+8)*SPA + c0)   = make_float2(h2, h3);
            *(float2*)(Pwl + g*SPA + c0)       = make_float2(tf32h(p0 - h0), tf32h(p1 - h1));
            *(float2*)(Pwl + (g+8)*SPA + c0)   = make_float2(tf32h(p2 - h2), tf32h(p3 - h3));
        }
        rs0 += __shfl_xor_sync(0xffffffffu, rs0, 1);
        rs0 += __shfl_xor_sync(0xffffffffu, rs0, 2);
        rs1 += __shfl_xor_sync(0xffffffffu, rs1, 1);
        rs1 += __shfl_xor_sync(0xffffffffu, rs1, 2);
        l0 = l0*a0 + rs0;
        l1 = l1*a1 + rs1;
        m0 = m0n; m1 = m1n;
        #pragma unroll
        for (int j = 0; j < 8; j++) {
            o[j][0] *= a0; o[j][1] *= a0; o[j][2] *= a1; o[j][3] *= a1;
        }
        __syncwarp();

        // ---- O += P V ----
        #pragma unroll
        for (int kk = 0; kk < 8; kk++) {
            float ah[4], al[4];
            const float* ph = Phi + (w*16 + g)*SPA + kk*8 + t;
            const float* pl = Plo + (w*16 + g)*SPA + kk*8 + t;
            ah[0] = ph[0]; ah[1] = ph[8*SPA]; ah[2] = ph[4]; ah[3] = ph[8*SPA + 4];
            al[0] = pl[0]; al[1] = pl[8*SPA]; al[2] = pl[4]; al[3] = pl[8*SPA + 4];
            #pragma unroll
            for (int j = 0; j < 8; j++) {
                const float* vh = Vhi + (kk*8 + t)*SVA + j*8 + g;
                const float* vl = Vlo + (kk*8 + t)*SVA + j*8 + g;
                float bh0 = vh[0], bh1 = vh[4*SVA];
                float bl0 = vl[0], bl1 = vl[4*SVA];
                mma8(o[j], ah, bh0, bh1);
                mma8(o[j], al, bh0, bh1);
                mma8(o[j], ah, bl0, bl1);
            }
        }
    }

    float inv0 = 1.f / l0, inv1 = 1.f / l1;
    int row0 = q0 + w*16 + g;
    #pragma unroll
    for (int j = 0; j < 8; j++) {
        int col = h*64 + j*8 + 2*t;
        *(float2*)(out + (size_t)(b*SQ + row0)*DD + col) =
            make_float2(o[j][0]*inv0, o[j][1]*inv0);
        *(float2*)(out + (size_t)(b*SQ + row0 + 8)*DD + col) =
            make_float2(o[j][2]*inv1, o[j][3]*inv1);
    }
}

// ---------------- launch ----------------
extern "C" void kernel_launch(void* const* d_in, const int* in_sizes, int n_in,
                              void* d_out, int out_size)
{
    const float* x         = (const float*)d_in[0];
    const float* h_prev    = (const float*)d_in[1];
    const float* norm1_w   = (const float*)d_in[2];
    const float* norm2_w   = (const float*)d_in[3];
    const float* decay     = (const float*)d_in[4];
    const float* rec_W     = (const float*)d_in[5];
    const float* rec_b     = (const float*)d_in[6];
    const float* in_proj_w = (const float*)d_in[7];
    const float* in_proj_b = (const float*)d_in[8];
    const float* out_w     = (const float*)d_in[9];
    const float* out_b     = (const float*)d_in[10];
    const float* conv_w    = (const float*)d_in[11];
    const float* conv_b    = (const float*)d_in[12];
    const float* w1_W      = (const float*)d_in[13];
    const float* w1_b      = (const float*)d_in[14];
    const float* w2_W      = (const float*)d_in[15];
    const float* w2_b      = (const float*)d_in[16];
    const float* w3_W      = (const float*)d_in[17];
    const float* w3_b      = (const float*)d_in[18];

    float* out_x    = (float*)d_out;
    float* out_hrec = out_x + NELEM;

    float *nx, *nx2, *qkv, *attnpre, *hattn, *xbuf, *ff1, *ff2;
    cudaGetSymbolAddress((void**)&nx,      g_nx);
    cudaGetSymbolAddress((void**)&nx2,     g_nx2);
    cudaGetSymbolAddress((void**)&qkv,     g_qkv);
    cudaGetSymbolAddress((void**)&attnpre, g_attnpre);
    cudaGetSymbolAddress((void**)&hattn,   g_hattn);
    cudaGetSymbolAddress((void**)&xbuf,    g_xbuf);
    cudaGetSymbolAddress((void**)&ff1,     g_ff1);
    cudaGetSymbolAddress((void**)&ff2,     g_ff2);

    const int SM0 = 2*4*TILEF*4;   // MODE0: 81920 B
    const int SM1 = 2*3*TILEF*4;   // MODE1: 61440 B
    cudaFuncSetAttribute(mma_gemm<0,0>, cudaFuncAttributeMaxDynamicSharedMemorySize, SM0);
    cudaFuncSetAttribute(mma_gemm<1,0>, cudaFuncAttributeMaxDynamicSharedMemorySize, SM1);
    cudaFuncSetAttribute(mma_gemm<1,1>, cudaFuncAttributeMaxDynamicSharedMemorySize, SM1);
    cudaFuncSetAttribute(mma_gemm<1,2>, cudaFuncAttributeMaxDynamicSharedMemorySize, SM1);
    cudaFuncSetAttribute(attn_mma, cudaFuncAttributeMaxDynamicSharedMemorySize, ATTN_SMEM);

    zero_absmax_kernel<<<1, 32>>>();
    rmsnorm_kernel<<<ROWS, 256>>>(x, norm1_w, nx, 0);
    quant_kernel<<<2048, 256>>>(nx, nx2, 0, NELEM/4);
    // qkv = nx @ in_proj_w^T + b   (tf32x3)
    mma_gemm<0,0><<<dim3(24, 64), 256, SM0>>>(nx, in_proj_w, in_proj_b, qkv,
                                              ROWS, 3072, 1024, nullptr, nullptr, -1);
    // h_rec = tanh(scale0*(codes @ rec_W^T) + rec_b + exp(decay)*h_prev)
    mma_gemm<1,1><<<dim3(8, 64), 256, SM1>>>(nx2, rec_W, rec_b, out_hrec,
                                             ROWS, 1024, 1024, h_prev, decay, 0);
    // flash attention (tensor cores)
    attn_mma<<<dim3(16, 16, 4), 256, ATTN_SMEM>>>(qkv, attnpre);
    // out projection (tf32x3)
    mma_gemm<0,0><<<dim3(8, 64), 256, SM0>>>(attnpre, out_w, out_b, hattn,
                                             ROWS, 1024, 1024, nullptr, nullptr, -1);
    conv_combine_kernel<<<ROWS, 256>>>(x, out_hrec, hattn, nx, conv_w, conv_b, xbuf);
    rmsnorm_kernel<<<ROWS, 256>>>(xbuf, norm2_w, nx2, 1);
    quant_kernel<<<2048, 256>>>(nx2, nx2, 1, NELEM/4);
    mma_gemm<1,0><<<dim3(32, 64), 256, SM1>>>(nx2, w1_W, w1_b, ff1,
                                              ROWS, 4096, 1024, nullptr, nullptr, 1);
    mma_gemm<1,0><<<dim3(32, 64), 256, SM1>>>(nx2, w2_W, w2_b, ff2,
                                              ROWS, 4096, 1024, nullptr, nullptr, 1);
    gate_kernel<<<4096, 256>>>(ff1, ff2, (ROWS*4096)/4, 2);
    quant_kernel<<<4096, 256>>>(ff1, ff1, 2, (ROWS*4096)/4);
    mma_gemm<1,2><<<dim3(8, 64), 256, SM1>>>(ff1, w3_W, w3_b, out_x,
                                             ROWS, 1024, 4096, xbuf, nullptr, 2);
}

// round 6
// speedup vs baseline: 2.5324x; 1.0612x over previous
#include <cuda_runtime.h>
#include <cstdint>

#define DD 1024
#define NB 4
#define SQ 2048
#define ROWS (NB*SQ)            /* 8192 */
#define NELEM (ROWS*DD)         /* 8388608 */

// ---------------- scratch ----------------
__device__ float g_absmax[4];
__device__ float g_nx[NELEM];
__device__ float g_nx2[NELEM];
__device__ float g_qkv[ROWS*3*DD];
__device__ float g_attnpre[NELEM];
__device__ float g_hattn[NELEM];
__device__ float g_xbuf[NELEM];
__device__ float g_ff1[ROWS*4*DD];
__device__ float g_ff2[ROWS*4*DD];

// ---------------- helpers ----------------
__device__ __forceinline__ float tf32h(float x){
    uint32_t r; asm("cvt.rna.tf32.f32 %0, %1;" : "=r"(r) : "f"(x));
    return __uint_as_float(r);
}
// fast exp: exp(x) = 2^(x*log2e), poly on [-0.5,0.5], rel err ~2e-6
__device__ __forceinline__ float fexp(float x){
    float y = x * 1.4426950408889634f;
    y = fminf(fmaxf(y, -120.f), 120.f);
    float r = rintf(y);
    float f = y - r;
    float p = 1.f + f*(0.6931471805599453f + f*(0.2402265069591007f +
              f*(0.05550410866482158f + f*(0.009618129107628477f +
              f*0.0013333558146428443f))));
    return __int_as_float(__float_as_int(p) + (((int)r) << 23));
}
__device__ __forceinline__ void mma8(float (&d)[4], const float* a, float b0, float b1){
    asm volatile("mma.sync.aligned.m16n8k8.row.col.f32.tf32.tf32.f32 "
        "{%0,%1,%2,%3},{%4,%5,%6,%7},{%8,%9},{%0,%1,%2,%3};"
        : "+f"(d[0]),"+f"(d[1]),"+f"(d[2]),"+f"(d[3])
        : "r"(__float_as_uint(a[0])),"r"(__float_as_uint(a[1])),
          "r"(__float_as_uint(a[2])),"r"(__float_as_uint(a[3])),
          "r"(__float_as_uint(b0)),"r"(__float_as_uint(b1)));
}

// ---------------- small kernels ----------------
__global__ void zero_absmax_kernel() {
    if (threadIdx.x < 4) g_absmax[threadIdx.x] = 0.f;
}

__global__ void __launch_bounds__(256) rmsnorm_kernel(
    const float* __restrict__ x, const float* __restrict__ w,
    float* __restrict__ out, int slot)
{
    __shared__ float red[256];
    int tid = threadIdx.x;
    size_t row = blockIdx.x;
    float4 xv = ((const float4*)(x + row*DD))[tid];
    float ss = xv.x*xv.x + xv.y*xv.y + xv.z*xv.z + xv.w*xv.w;
    red[tid] = ss;
    __syncthreads();
    #pragma unroll
    for (int s = 128; s > 0; s >>= 1) {
        if (tid < s) red[tid] += red[tid + s];
        __syncthreads();
    }
    float rinv = rsqrtf(red[0] * (1.f/1024.f) + 1e-6f);
    __syncthreads();
    float4 wv = ((const float4*)w)[tid];
    float4 o;
    o.x = wv.x * (xv.x * rinv);
    o.y = wv.y * (xv.y * rinv);
    o.z = wv.z * (xv.z * rinv);
    o.w = wv.w * (xv.w * rinv);
    ((float4*)(out + row*DD))[tid] = o;
    float am = fmaxf(fmaxf(fabsf(o.x), fabsf(o.y)), fmaxf(fabsf(o.z), fabsf(o.w)));
    red[tid] = am;
    __syncthreads();
    #pragma unroll
    for (int s = 128; s > 0; s >>= 1) {
        if (tid < s) red[tid] = fmaxf(red[tid], red[tid + s]);
        __syncthreads();
    }
    if (tid == 0) atomicMax((int*)&g_absmax[slot], __float_as_int(red[0]));
}

__global__ void __launch_bounds__(256) quant_kernel(
    const float* __restrict__ in, float* __restrict__ out, int slot, int n4)
{
    float scale = g_absmax[slot] / 127.0f + 1e-8f;
    int stride = gridDim.x * blockDim.x;
    for (int i = blockIdx.x*blockDim.x + threadIdx.x; i < n4; i += stride) {
        float4 v = ((const float4*)in)[i];
        v.x = fminf(fmaxf(rintf(v.x / scale), -128.f), 127.f);
        v.y = fminf(fmaxf(rintf(v.y / scale), -128.f), 127.f);
        v.z = fminf(fmaxf(rintf(v.z / scale), -128.f), 127.f);
        v.w = fminf(fmaxf(rintf(v.w / scale), -128.f), 127.f);
        ((float4*)out)[i] = v;
    }
}

__global__ void __launch_bounds__(256) gate_kernel(
    float* __restrict__ a, const float* __restrict__ bsrc, int n4, int slot)
{
    __shared__ float red[256];
    float am = 0.f;
    int stride = gridDim.x * blockDim.x;
    for (int i = blockIdx.x*blockDim.x + threadIdx.x; i < n4; i += stride) {
        float4 u = ((const float4*)a)[i];
        float4 v = ((const float4*)bsrc)[i];
        float4 g;
        g.x = u.x / (1.f + fexp(-u.x)) * v.x;
        g.y = u.y / (1.f + fexp(-u.y)) * v.y;
        g.z = u.z / (1.f + fexp(-u.z)) * v.z;
        g.w = u.w / (1.f + fexp(-u.w)) * v.w;
        ((float4*)a)[i] = g;
        am = fmaxf(am, fmaxf(fmaxf(fabsf(g.x), fabsf(g.y)), fmaxf(fabsf(g.z), fabsf(g.w))));
    }
    red[threadIdx.x] = am;
    __syncthreads();
    #pragma unroll
    for (int s = 128; s > 0; s >>= 1) {
        if (threadIdx.x < s) red[threadIdx.x] = fmaxf(red[threadIdx.x], red[threadIdx.x + s]);
        __syncthreads();
    }
    if (threadIdx.x == 0) atomicMax((int*)&g_absmax[slot], __float_as_int(red[0]));
}

__global__ void __launch_bounds__(256) conv_combine_kernel(
    const float* __restrict__ x, const float* __restrict__ hrec,
    const float* __restrict__ hattn, const float* __restrict__ nx,
    const float* __restrict__ conv_w, const float* __restrict__ conv_b,
    float* __restrict__ xout)
{
    int bs = blockIdx.x;
    int b = bs >> 11;
    int s = bs & 2047;
    size_t rowbase = (size_t)bs * DD;
    for (int d = threadIdx.x; d < DD; d += 256) {
        float acc = conv_b[d];
        #pragma unroll
        for (int t = 0; t < 5; t++) {
            int ssi = s + t - 2;
            if (ssi >= 0 && ssi < SQ)
                acc = fmaf(nx[((size_t)b*SQ + ssi)*DD + d], conv_w[d*5 + t], acc);
        }
        size_t idx = rowbase + d;
        xout[idx] = x[idx] + hrec[idx] + hattn[idx] + acc;
    }
}

// ================= mma.sync tf32 GEMM (fused hi/lo passes, KC=32) =================
#define KC 32
#define SROW 36
#define TILEF (128*SROW)   /* 4608 floats per tile */

// MODE 0: split A & B, 3 products per fragment set.  MODE 1: A raw codes, 2 products.
// EPI 0: v.  EPI 1: tanh(v + exp(e2[n])*e1[m,n]).  EPI 2: v + e1[m,n].
template<int MODE, int EPI>
__global__ void __launch_bounds__(256) mma_gemm(
    const float* __restrict__ A, const float* __restrict__ W,
    const float* __restrict__ bias, float* __restrict__ C,
    int M, int N, int K,
    const float* __restrict__ e1, const float* __restrict__ e2, int slot)
{
    extern __shared__ float smem_f[];
    const int NT = (MODE == 0) ? 4 : 3;

    int tid = threadIdx.x;
    int wid = tid >> 5, lane = tid & 31;
    int wm = (wid & 1) * 64;
    int wn = (wid >> 1) * 32;
    int m0 = blockIdx.y * 128, n0 = blockIdx.x * 128;
    int lrow = tid >> 3, lc4 = (tid & 7) * 4;
    int g = lane >> 2, t4 = lane & 3;

    float d[4][4][4];
    #pragma unroll
    for (int i = 0; i < 4; i++)
        #pragma unroll
        for (int j = 0; j < 4; j++)
            #pragma unroll
            for (int q = 0; q < 4; q++) d[i][j][q] = 0.f;

    float4 av[4], wv[4];
    auto LDG = [&](int t){
        int k0 = t*KC + lc4;
        #pragma unroll
        for (int h = 0; h < 4; h++) {
            av[h] = *(const float4*)(A + (size_t)(m0 + lrow + h*32)*K + k0);
            wv[h] = *(const float4*)(W + (size_t)(n0 + lrow + h*32)*K + k0);
        }
    };
    auto STS = [&](int s){   // s = stage index (0/1)
        float* bufA = smem_f + (size_t)s*NT*TILEF;
        float* bufB = bufA + ((MODE == 0) ? 2 : 1)*TILEF;
        #pragma unroll
        for (int h = 0; h < 4; h++) {
            int off = (lrow + h*32)*SROW + lc4;
            if (MODE == 0) {
                float4 hi, lo;
                hi.x = tf32h(av[h].x); hi.y = tf32h(av[h].y);
                hi.z = tf32h(av[h].z); hi.w = tf32h(av[h].w);
                lo.x = tf32h(av[h].x - hi.x); lo.y = tf32h(av[h].y - hi.y);
                lo.z = tf32h(av[h].z - hi.z); lo.w = tf32h(av[h].w - hi.w);
                *(float4*)(bufA + off) = hi;
                *(float4*)(bufA + TILEF + off) = lo;
            } else {
                *(float4*)(bufA + off) = av[h];
            }
            float4 hi, lo;
            hi.x = tf32h(wv[h].x); hi.y = tf32h(wv[h].y);
            hi.z = tf32h(wv[h].z); hi.w = tf32h(wv[h].w);
            lo.x = tf32h(wv[h].x - hi.x); lo.y = tf32h(wv[h].y - hi.y);
            lo.z = tf32h(wv[h].z - hi.z); lo.w = tf32h(wv[h].w - hi.w);
            *(float4*)(bufB + off) = hi;
            *(float4*)(bufB + TILEF + off) = lo;
        }
    };

    const int T = K / KC;
    LDG(0); STS(0);
    if (T > 1) LDG(1);
    __syncthreads();

    for (int t = 0; t < T; t++) {
        const float* buf = smem_f + (size_t)(t & 1)*NT*TILEF;
        const float* Ahi = buf;
        const float* Alo = buf + TILEF;                          // MODE0 only
        const float* Bhi = buf + ((MODE == 0) ? 2 : 1)*TILEF;
        const float* Blo = Bhi + TILEF;

        #pragma unroll
        for (int kk = 0; kk < KC; kk += 8) {
            float ah[4][4], al[4][4];
            #pragma unroll
            for (int i = 0; i < 4; i++) {
                const float* base = Ahi + (wm + i*16 + g)*SROW + kk + t4;
                ah[i][0] = base[0];
                ah[i][1] = base[8*SROW];
                ah[i][2] = base[4];
                ah[i][3] = base[8*SROW + 4];
                if (MODE == 0) {
                    const float* base2 = Alo + (wm + i*16 + g)*SROW + kk + t4;
                    al[i][0] = base2[0];
                    al[i][1] = base2[8*SROW];
                    al[i][2] = base2[4];
                    al[i][3] = base2[8*SROW + 4];
                }
            }
            float bh[4][2], bl[4][2];
            #pragma unroll
            for (int j = 0; j < 4; j++) {
                const float* bb = Bhi + (wn + j*8 + g)*SROW + kk + t4;
                bh[j][0] = bb[0]; bh[j][1] = bb[4];
                const float* bb2 = Blo + (wn + j*8 + g)*SROW + kk + t4;
                bl[j][0] = bb2[0]; bl[j][1] = bb2[4];
            }
            #pragma unroll
            for (int i = 0; i < 4; i++)
                #pragma unroll
                for (int j = 0; j < 4; j++) {
                    mma8(d[i][j], ah[i], bh[j][0], bh[j][1]);
                    if (MODE == 0) mma8(d[i][j], al[i], bh[j][0], bh[j][1]);
                    mma8(d[i][j], ah[i], bl[j][0], bl[j][1]);
                }
        }

        if (t + 1 < T) {
            STS((t + 1) & 1);
            if (t + 2 < T) LDG(t + 2);
        }
        __syncthreads();
    }

    // epilogue
    float alpha = 1.f;
    if (slot >= 0) alpha = g_absmax[slot] * (1.f/127.f) + 1e-8f;
    int r = lane >> 2, c2 = (lane & 3) * 2;

    #pragma unroll
    for (int j = 0; j < 4; j++) {
        int cc = n0 + wn + j*8 + c2;
        float b0 = bias[cc], b1 = bias[cc + 1];
        float dn0 = 0.f, dn1 = 0.f;
        if (EPI == 1) { dn0 = expf(e2[cc]); dn1 = expf(e2[cc + 1]); }
        #pragma unroll
        for (int i = 0; i < 4; i++) {
            int r0 = m0 + wm + i*16 + r;
            #pragma unroll
            for (int half = 0; half < 2; half++) {
                int rr = r0 + half*8;
                size_t idx = (size_t)rr*N + cc;
                float v0 = alpha * d[i][j][half*2 + 0] + b0;
                float v1 = alpha * d[i][j][half*2 + 1] + b1;
                if (EPI == 1) {
                    v0 = tanhf(v0 + dn0 * e1[idx]);
                    v1 = tanhf(v1 + dn1 * e1[idx + 1]);
                } else if (EPI == 2) {
                    v0 += e1[idx];
                    v1 += e1[idx + 1];
                }
                float2 o; o.x = v0; o.y = v1;
                *(float2*)(C + idx) = o;
            }
        }
    }
}

// ================= MMA flash attention (tf32 x3) =================
// block: 128 q-rows x 1 head; 8 warps x 16 rows. K-tile = 64 keys.
#define SKA 68
#define SVA 72
#define SPA 68
#define OFF_KLO 4352
#define OFF_VHI 8704
#define OFF_VLO 13312
#define OFF_PHI 17920
#define OFF_PLO 26624
#define ATTN_SMEM (35328*4)

__global__ void __launch_bounds__(256) attn_mma(
    const float* __restrict__ qkv, float* __restrict__ out)
{
    extern __shared__ float smem_f[];
    float* Khi = smem_f;
    float* Klo = smem_f + OFF_KLO;
    float* Vhi = smem_f + OFF_VHI;
    float* Vlo = smem_f + OFF_VLO;
    float* Phi = smem_f + OFF_PHI;
    float* Plo = smem_f + OFF_PLO;

    int tid = threadIdx.x, w = tid >> 5, lane = tid & 31;
    int g = lane >> 2, t = lane & 3;
    int q0 = blockIdx.x * 128, h = blockIdx.y, b = blockIdx.z;
    const float* base = qkv + (size_t)b*SQ*3072 + h*64;

    // load Q (scaled by 1/8) into Phi region, then pull fragments into regs
    for (int i = tid; i < 2048; i += 256) {
        int row = i >> 4, c4 = (i & 15) * 4;
        float4 v = *(const float4*)(base + (size_t)(q0 + row)*3072 + c4);
        v.x *= 0.125f; v.y *= 0.125f; v.z *= 0.125f; v.w *= 0.125f;
        *(float4*)(Phi + row*SPA + c4) = v;
    }
    __syncthreads();

    float qh[8][4], ql[8][4];
    {
        const float* Qw = Phi + (w*16)*SPA;
        #pragma unroll
        for (int kk = 0; kk < 8; kk++) {
            #pragma unroll
            for (int q = 0; q < 4; q++) {
                int row = (q & 1) ? (g + 8) : g;
                int col = kk*8 + t + ((q & 2) ? 4 : 0);
                float x = Qw[row*SPA + col];
                qh[kk][q] = tf32h(x);
                ql[kk][q] = tf32h(x - qh[kk][q]);
            }
        }
    }

    float o[8][4];
    #pragma unroll
    for (int j = 0; j < 8; j++)
        #pragma unroll
        for (int q = 0; q < 4; q++) o[j][q] = 0.f;
    float m0 = -1e30f, m1 = -1e30f, l0 = 0.f, l1 = 0.f;

    for (int kt = 0; kt < SQ/64; kt++) {
        __syncthreads();
        for (int i = tid; i < 1024; i += 256) {
            int row = i >> 4, c4 = (i & 15) * 4;
            const float* gp = base + (size_t)(kt*64 + row)*3072 + 1024 + c4;
            float4 kv = *(const float4*)gp;
            float4 vv = *(const float4*)(gp + 1024);
            float4 khv, klv, vhv, vlv;
            khv.x = tf32h(kv.x); khv.y = tf32h(kv.y); khv.z = tf32h(kv.z); khv.w = tf32h(kv.w);
            klv.x = tf32h(kv.x - khv.x); klv.y = tf32h(kv.y - khv.y);
            klv.z = tf32h(kv.z - khv.z); klv.w = tf32h(kv.w - khv.w);
            vhv.x = tf32h(vv.x); vhv.y = tf32h(vv.y); vhv.z = tf32h(vv.z); vhv.w = tf32h(vv.w);
            vlv.x = tf32h(vv.x - vhv.x); vlv.y = tf32h(vv.y - vhv.y);
            vlv.z = tf32h(vv.z - vhv.z); vlv.w = tf32h(vv.w - vhv.w);
            *(float4*)(Khi + row*SKA + c4) = khv;
            *(float4*)(Klo + row*SKA + c4) = klv;
            *(float4*)(Vhi + row*SVA + c4) = vhv;
            *(float4*)(Vlo + row*SVA + c4) = vlv;
        }
        __syncthreads();

        // ---- S = Q K^T ----
        float s[8][4];
        #pragma unroll
        for (int j = 0; j < 8; j++)
            #pragma unroll
            for (int q = 0; q < 4; q++) s[j][q] = 0.f;

        #pragma unroll
        for (int j = 0; j < 8; j++) {
            #pragma unroll
            for (int kk = 0; kk < 8; kk++) {
                const float* kh = Khi + (j*8 + g)*SKA + kk*8 + t;
                const float* kl = Klo + (j*8 + g)*SKA + kk*8 + t;
                float bh0 = kh[0], bh1 = kh[4];
                float bl0 = kl[0], bl1 = kl[4];
                mma8(s[j], qh[kk], bh0, bh1);
                mma8(s[j], ql[kk], bh0, bh1);
                mma8(s[j], qh[kk], bl0, bl1);
            }
        }

        // ---- online softmax ----
        float mt0 = -1e30f, mt1 = -1e30f;
        #pragma unroll
        for (int j = 0; j < 8; j++) {
            mt0 = fmaxf(mt0, fmaxf(s[j][0], s[j][1]));
            mt1 = fmaxf(mt1, fmaxf(s[j][2], s[j][3]));
        }
        mt0 = fmaxf(mt0, __shfl_xor_sync(0xffffffffu, mt0, 1));
        mt0 = fmaxf(mt0, __shfl_xor_sync(0xffffffffu, mt0, 2));
        mt1 = fmaxf(mt1, __shfl_xor_sync(0xffffffffu, mt1, 1));
        mt1 = fmaxf(mt1, __shfl_xor_sync(0xffffffffu, mt1, 2));
        float m0n = fmaxf(m0, mt0), m1n = fmaxf(m1, mt1);
        float a0 = fexp(m0 - m0n), a1 = fexp(m1 - m1n);

        float rs0 = 0.f, rs1 = 0.f;
        float* Pwh = Phi + (w*16)*SPA;
        float* Pwl = Plo + (w*16)*SPA;
        #pragma unroll
        for (int j = 0; j < 8; j++) {
            float p0 = fexp(s[j][0] - m0n), p1 = fexp(s[j][1] - m0n);
            float p2 = fexp(s[j][2] - m1n), p3 = fexp(s[j][3] - m1n);
            rs0 += p0 + p1; rs1 += p2 + p3;
            float h0 = tf32h(p0), h1 = tf32h(p1), h2 = tf32h(p2), h3 = tf32h(p3);
            int c0 = j*8 + 2*t;
            *(float2*)(Pwh + g*SPA + c0)       = make_float2(h0, h1);
            *(float2*)(Pwh + (g+8)*SPA + c0)   = make_float2(h2, h3);
            *(float2*)(Pwl + g*SPA + c0)       = make_float2(tf32h(p0 - h0), tf32h(p1 - h1));
            *(float2*)(Pwl + (g+8)*SPA + c0)   = make_float2(tf32h(p2 - h2), tf32h(p3 - h3));
        }
        rs0 += __shfl_xor_sync(0xffffffffu, rs0, 1);
        rs0 += __shfl_xor_sync(0xffffffffu, rs0, 2);
        rs1 += __shfl_xor_sync(0xffffffffu, rs1, 1);
        rs1 += __shfl_xor_sync(0xffffffffu, rs1, 2);
        l0 = l0*a0 + rs0;
        l1 = l1*a1 + rs1;
        m0 = m0n; m1 = m1n;
        #pragma unroll
        for (int j = 0; j < 8; j++) {
            o[j][0] *= a0; o[j][1] *= a0; o[j][2] *= a1; o[j][3] *= a1;
        }
        __syncwarp();

        // ---- O += P V ----
        #pragma unroll
        for (int kk = 0; kk < 8; kk++) {
            float ah[4], al[4];
            const float* ph = Phi + (w*16 + g)*SPA + kk*8 + t;
            const float* pl = Plo + (w*16 + g)*SPA + kk*8 + t;
            ah[0] = ph[0]; ah[1] = ph[8*SPA]; ah[2] = ph[4]; ah[3] = ph[8*SPA + 4];
            al[0] = pl[0]; al[1] = pl[8*SPA]; al[2] = pl[4]; al[3] = pl[8*SPA + 4];
            #pragma unroll
            for (int j = 0; j < 8; j++) {
                const float* vh = Vhi + (kk*8 + t)*SVA + j*8 + g;
                const float* vl = Vlo + (kk*8 + t)*SVA + j*8 + g;
                float bh0 = vh[0], bh1 = vh[4*SVA];
                float bl0 = vl[0], bl1 = vl[4*SVA];
                mma8(o[j], ah, bh0, bh1);
                mma8(o[j], al, bh0, bh1);
                mma8(o[j], ah, bl0, bl1);
            }
        }
    }

    float inv0 = 1.f / l0, inv1 = 1.f / l1;
    int row0 = q0 + w*16 + g;
    #pragma unroll
    for (int j = 0; j < 8; j++) {
        int col = h*64 + j*8 + 2*t;
        *(float2*)(out + (size_t)(b*SQ + row0)*DD + col) =
            make_float2(o[j][0]*inv0, o[j][1]*inv0);
        *(float2*)(out + (size_t)(b*SQ + row0 + 8)*DD + col) =
            make_float2(o[j][2]*inv1, o[j][3]*inv1);
    }
}

// ---------------- launch ----------------
extern "C" void kernel_launch(void* const* d_in, const int* in_sizes, int n_in,
                              void* d_out, int out_size)
{
    const float* x         = (const float*)d_in[0];
    const float* h_prev    = (const float*)d_in[1];
    const float* norm1_w   = (const float*)d_in[2];
    const float* norm2_w   = (const float*)d_in[3];
    const float* decay     = (const float*)d_in[4];
    const float* rec_W     = (const float*)d_in[5];
    const float* rec_b     = (const float*)d_in[6];
    const float* in_proj_w = (const float*)d_in[7];
    const float* in_proj_b = (const float*)d_in[8];
    const float* out_w     = (const float*)d_in[9];
    const float* out_b     = (const float*)d_in[10];
    const float* conv_w    = (const float*)d_in[11];
    const float* conv_b    = (const float*)d_in[12];
    const float* w1_W      = (const float*)d_in[13];
    const float* w1_b      = (const float*)d_in[14];
    const float* w2_W      = (const float*)d_in[15];
    const float* w2_b      = (const float*)d_in[16];
    const float* w3_W      = (const float*)d_in[17];
    const float* w3_b      = (const float*)d_in[18];

    float* out_x    = (float*)d_out;
    float* out_hrec = out_x + NELEM;

    float *nx, *nx2, *qkv, *attnpre, *hattn, *xbuf, *ff1, *ff2;
    cudaGetSymbolAddress((void**)&nx,      g_nx);
    cudaGetSymbolAddress((void**)&nx2,     g_nx2);
    cudaGetSymbolAddress((void**)&qkv,     g_qkv);
    cudaGetSymbolAddress((void**)&attnpre, g_attnpre);
    cudaGetSymbolAddress((void**)&hattn,   g_hattn);
    cudaGetSymbolAddress((void**)&xbuf,    g_xbuf);
    cudaGetSymbolAddress((void**)&ff1,     g_ff1);
    cudaGetSymbolAddress((void**)&ff2,     g_ff2);

    const int SM0 = 2*4*TILEF*4;   // MODE0: 147456 B
    const int SM1 = 2*3*TILEF*4;   // MODE1: 110592 B
    cudaFuncSetAttribute(mma_gemm<0,0>, cudaFuncAttributeMaxDynamicSharedMemorySize, SM0);
    cudaFuncSetAttribute(mma_gemm<1,0>, cudaFuncAttributeMaxDynamicSharedMemorySize, SM1);
    cudaFuncSetAttribute(mma_gemm<1,1>, cudaFuncAttributeMaxDynamicSharedMemorySize, SM1);
    cudaFuncSetAttribute(mma_gemm<1,2>, cudaFuncAttributeMaxDynamicSharedMemorySize, SM1);
    cudaFuncSetAttribute(attn_mma, cudaFuncAttributeMaxDynamicSharedMemorySize, ATTN_SMEM);

    zero_absmax_kernel<<<1, 32>>>();
    rmsnorm_kernel<<<ROWS, 256>>>(x, norm1_w, nx, 0);
    quant_kernel<<<2048, 256>>>(nx, nx2, 0, NELEM/4);
    // qkv = nx @ in_proj_w^T + b   (tf32x3)
    mma_gemm<0,0><<<dim3(24, 64), 256, SM0>>>(nx, in_proj_w, in_proj_b, qkv,
                                              ROWS, 3072, 1024, nullptr, nullptr, -1);
    // h_rec = tanh(scale0*(codes @ rec_W^T) + rec_b + exp(decay)*h_prev)
    mma_gemm<1,1><<<dim3(8, 64), 256, SM1>>>(nx2, rec_W, rec_b, out_hrec,
                                             ROWS, 1024, 1024, h_prev, decay, 0);
    // flash attention (tensor cores)
    attn_mma<<<dim3(16, 16, 4), 256, ATTN_SMEM>>>(qkv, attnpre);
    // out projection (tf32x3)
    mma_gemm<0,0><<<dim3(8, 64), 256, SM0>>>(attnpre, out_w, out_b, hattn,
                                             ROWS, 1024, 1024, nullptr, nullptr, -1);
    conv_combine_kernel<<<ROWS, 256>>>(x, out_hrec, hattn, nx, conv_w, conv_b, xbuf);
    rmsnorm_kernel<<<ROWS, 256>>>(xbuf, norm2_w, nx2, 1);
    quant_kernel<<<2048, 256>>>(nx2, nx2, 1, NELEM/4);
    mma_gemm<1,0><<<dim3(32, 64), 256, SM1>>>(nx2, w1_W, w1_b, ff1,
                                              ROWS, 4096, 1024, nullptr, nullptr, 1);
    mma_gemm<1,0><<<dim3(32, 64), 256, SM1>>>(nx2, w2_W, w2_b, ff2,
                                              ROWS, 4096, 1024, nullptr, nullptr, 1);
    gate_kernel<<<4096, 256>>>(ff1, ff2, (ROWS*4096)/4, 2);
    quant_kernel<<<4096, 256>>>(ff1, ff1, 2, (ROWS*4096)/4);
    mma_gemm<1,2><<<dim3(8, 64), 256, SM1>>>(ff1, w3_W, w3_b, out_x,
                                             ROWS, 1024, 4096, xbuf, nullptr, 2);
}

// round 7
// speedup vs baseline: 3.1383x; 1.2393x over previous
#include <cuda_runtime.h>
#include <cstdint>

#define DD 1024
#define NB 4
#define SQ 2048
#define ROWS (NB*SQ)            /* 8192 */
#define NELEM (ROWS*DD)         /* 8388608 */

// ---------------- scratch ----------------
__device__ float g_absmax[4];
__device__ float g_nx[NELEM];
__device__ float g_nx2[NELEM];
__device__ float g_qkv[ROWS*3*DD];
__device__ float g_attnpre[NELEM];
__device__ float g_hattn[NELEM];
__device__ float g_xbuf[NELEM];
__device__ float g_ff1[ROWS*4*DD];
__device__ float g_ff2[ROWS*4*DD];

// ---------------- helpers ----------------
__device__ __forceinline__ float tf32h(float x){
    uint32_t r; asm("cvt.rna.tf32.f32 %0, %1;" : "=r"(r) : "f"(x));
    return __uint_as_float(r);
}
__device__ __forceinline__ uint32_t packbf(float lo, float hi){
    uint32_t r; asm("cvt.rn.bf16x2.f32 %0, %1, %2;" : "=r"(r) : "f"(hi), "f"(lo));
    return r;
}
// fast exp: exp(x) = 2^(x*log2e), poly on [-0.5,0.5], rel err ~2e-6
__device__ __forceinline__ float fexp(float x){
    float y = x * 1.4426950408889634f;
    y = fminf(fmaxf(y, -120.f), 120.f);
    float r = rintf(y);
    float f = y - r;
    float p = 1.f + f*(0.6931471805599453f + f*(0.2402265069591007f +
              f*(0.05550410866482158f + f*(0.009618129107628477f +
              f*0.0013333558146428443f))));
    return __int_as_float(__float_as_int(p) + (((int)r) << 23));
}
__device__ __forceinline__ void mma8(float (&d)[4], const float* a, float b0, float b1){
    asm volatile("mma.sync.aligned.m16n8k8.row.col.f32.tf32.tf32.f32 "
        "{%0,%1,%2,%3},{%4,%5,%6,%7},{%8,%9},{%0,%1,%2,%3};"
        : "+f"(d[0]),"+f"(d[1]),"+f"(d[2]),"+f"(d[3])
        : "r"(__float_as_uint(a[0])),"r"(__float_as_uint(a[1])),
          "r"(__float_as_uint(a[2])),"r"(__float_as_uint(a[3])),
          "r"(__float_as_uint(b0)),"r"(__float_as_uint(b1)));
}
__device__ __forceinline__ void mma16(float (&d)[4], const uint32_t* a, uint32_t b0, uint32_t b1){
    asm volatile("mma.sync.aligned.m16n8k16.row.col.f32.bf16.bf16.f32 "
        "{%0,%1,%2,%3},{%4,%5,%6,%7},{%8,%9},{%0,%1,%2,%3};"
        : "+f"(d[0]),"+f"(d[1]),"+f"(d[2]),"+f"(d[3])
        : "r"(a[0]),"r"(a[1]),"r"(a[2]),"r"(a[3]),"r"(b0),"r"(b1));
}

// ---------------- small kernels ----------------
__global__ void zero_absmax_kernel() {
    if (threadIdx.x < 4) g_absmax[threadIdx.x] = 0.f;
}

__global__ void __launch_bounds__(256) rmsnorm_kernel(
    const float* __restrict__ x, const float* __restrict__ w,
    float* __restrict__ out, int slot)
{
    __shared__ float red[256];
    int tid = threadIdx.x;
    size_t row = blockIdx.x;
    float4 xv = ((const float4*)(x + row*DD))[tid];
    float ss = xv.x*xv.x + xv.y*xv.y + xv.z*xv.z + xv.w*xv.w;
    red[tid] = ss;
    __syncthreads();
    #pragma unroll
    for (int s = 128; s > 0; s >>= 1) {
        if (tid < s) red[tid] += red[tid + s];
        __syncthreads();
    }
    float rinv = rsqrtf(red[0] * (1.f/1024.f) + 1e-6f);
    __syncthreads();
    float4 wv = ((const float4*)w)[tid];
    float4 o;
    o.x = wv.x * (xv.x * rinv);
    o.y = wv.y * (xv.y * rinv);
    o.z = wv.z * (xv.z * rinv);
    o.w = wv.w * (xv.w * rinv);
    ((float4*)(out + row*DD))[tid] = o;
    float am = fmaxf(fmaxf(fabsf(o.x), fabsf(o.y)), fmaxf(fabsf(o.z), fabsf(o.w)));
    red[tid] = am;
    __syncthreads();
    #pragma unroll
    for (int s = 128; s > 0; s >>= 1) {
        if (tid < s) red[tid] = fmaxf(red[tid], red[tid + s]);
        __syncthreads();
    }
    if (tid == 0) atomicMax((int*)&g_absmax[slot], __float_as_int(red[0]));
}

__global__ void __launch_bounds__(256) quant_kernel(
    const float* __restrict__ in, float* __restrict__ out, int slot, int n4)
{
    float scale = g_absmax[slot] / 127.0f + 1e-8f;
    int stride = gridDim.x * blockDim.x;
    for (int i = blockIdx.x*blockDim.x + threadIdx.x; i < n4; i += stride) {
        float4 v = ((const float4*)in)[i];
        v.x = fminf(fmaxf(rintf(v.x / scale), -128.f), 127.f);
        v.y = fminf(fmaxf(rintf(v.y / scale), -128.f), 127.f);
        v.z = fminf(fmaxf(rintf(v.z / scale), -128.f), 127.f);
        v.w = fminf(fmaxf(rintf(v.w / scale), -128.f), 127.f);
        ((float4*)out)[i] = v;
    }
}

__global__ void __launch_bounds__(256) gate_kernel(
    float* __restrict__ a, const float* __restrict__ bsrc, int n4, int slot)
{
    __shared__ float red[256];
    float am = 0.f;
    int stride = gridDim.x * blockDim.x;
    for (int i = blockIdx.x*blockDim.x + threadIdx.x; i < n4; i += stride) {
        float4 u = ((const float4*)a)[i];
        float4 v = ((const float4*)bsrc)[i];
        float4 g;
        g.x = u.x / (1.f + fexp(-u.x)) * v.x;
        g.y = u.y / (1.f + fexp(-u.y)) * v.y;
        g.z = u.z / (1.f + fexp(-u.z)) * v.z;
        g.w = u.w / (1.f + fexp(-u.w)) * v.w;
        ((float4*)a)[i] = g;
        am = fmaxf(am, fmaxf(fmaxf(fabsf(g.x), fabsf(g.y)), fmaxf(fabsf(g.z), fabsf(g.w))));
    }
    red[threadIdx.x] = am;
    __syncthreads();
    #pragma unroll
    for (int s = 128; s > 0; s >>= 1) {
        if (threadIdx.x < s) red[threadIdx.x] = fmaxf(red[threadIdx.x], red[threadIdx.x + s]);
        __syncthreads();
    }
    if (threadIdx.x == 0) atomicMax((int*)&g_absmax[slot], __float_as_int(red[0]));
}

__global__ void __launch_bounds__(256) conv_combine_kernel(
    const float* __restrict__ x, const float* __restrict__ hrec,
    const float* __restrict__ hattn, const float* __restrict__ nx,
    const float* __restrict__ conv_w, const float* __restrict__ conv_b,
    float* __restrict__ xout)
{
    int bs = blockIdx.x;
    int b = bs >> 11;
    int s = bs & 2047;
    size_t rowbase = (size_t)bs * DD;
    for (int d = threadIdx.x; d < DD; d += 256) {
        float acc = conv_b[d];
        #pragma unroll
        for (int t = 0; t < 5; t++) {
            int ssi = s + t - 2;
            if (ssi >= 0 && ssi < SQ)
                acc = fmaf(nx[((size_t)b*SQ + ssi)*DD + d], conv_w[d*5 + t], acc);
        }
        size_t idx = rowbase + d;
        xout[idx] = x[idx] + hrec[idx] + hattn[idx] + acc;
    }
}

// ================= tf32 x3 GEMM (fp32 activations: qkv, out-proj) =================
#define KC 32
#define SROW 36
#define TILEF (128*SROW)   /* 4608 floats per tile */

template<int EPI>
__global__ void __launch_bounds__(256) mma_gemm(
    const float* __restrict__ A, const float* __restrict__ W,
    const float* __restrict__ bias, float* __restrict__ C,
    int M, int N, int K,
    const float* __restrict__ e1, const float* __restrict__ e2, int slot)
{
    extern __shared__ float smem_f[];
    const int NT = 4;

    int tid = threadIdx.x;
    int wid = tid >> 5, lane = tid & 31;
    int wm = (wid & 1) * 64;
    int wn = (wid >> 1) * 32;
    int m0 = blockIdx.y * 128, n0 = blockIdx.x * 128;
    int lrow = tid >> 3, lc4 = (tid & 7) * 4;
    int g = lane >> 2, t4 = lane & 3;

    float d[4][4][4];
    #pragma unroll
    for (int i = 0; i < 4; i++)
        #pragma unroll
        for (int j = 0; j < 4; j++)
            #pragma unroll
            for (int q = 0; q < 4; q++) d[i][j][q] = 0.f;

    float4 av[4], wv[4];
    auto LDG = [&](int t){
        int k0 = t*KC + lc4;
        #pragma unroll
        for (int h = 0; h < 4; h++) {
            av[h] = *(const float4*)(A + (size_t)(m0 + lrow + h*32)*K + k0);
            wv[h] = *(const float4*)(W + (size_t)(n0 + lrow + h*32)*K + k0);
        }
    };
    auto STS = [&](int s){
        float* bufA = smem_f + (size_t)s*NT*TILEF;
        float* bufB = bufA + 2*TILEF;
        #pragma unroll
        for (int h = 0; h < 4; h++) {
            int off = (lrow + h*32)*SROW + lc4;
            float4 hi, lo;
            hi.x = tf32h(av[h].x); hi.y = tf32h(av[h].y);
            hi.z = tf32h(av[h].z); hi.w = tf32h(av[h].w);
            lo.x = tf32h(av[h].x - hi.x); lo.y = tf32h(av[h].y - hi.y);
            lo.z = tf32h(av[h].z - hi.z); lo.w = tf32h(av[h].w - hi.w);
            *(float4*)(bufA + off) = hi;
            *(float4*)(bufA + TILEF + off) = lo;
            hi.x = tf32h(wv[h].x); hi.y = tf32h(wv[h].y);
            hi.z = tf32h(wv[h].z); hi.w = tf32h(wv[h].w);
            lo.x = tf32h(wv[h].x - hi.x); lo.y = tf32h(wv[h].y - hi.y);
            lo.z = tf32h(wv[h].z - hi.z); lo.w = tf32h(wv[h].w - hi.w);
            *(float4*)(bufB + off) = hi;
            *(float4*)(bufB + TILEF + off) = lo;
        }
    };

    const int T = K / KC;
    LDG(0); STS(0);
    if (T > 1) LDG(1);
    __syncthreads();

    for (int t = 0; t < T; t++) {
        const float* buf = smem_f + (size_t)(t & 1)*NT*TILEF;
        const float* Ahi = buf;
        const float* Alo = buf + TILEF;
        const float* Bhi = buf + 2*TILEF;
        const float* Blo = buf + 3*TILEF;

        #pragma unroll
        for (int kk = 0; kk < KC; kk += 8) {
            float ah[4][4], al[4][4];
            #pragma unroll
            for (int i = 0; i < 4; i++) {
                const float* base = Ahi + (wm + i*16 + g)*SROW + kk + t4;
                ah[i][0] = base[0];
                ah[i][1] = base[8*SROW];
                ah[i][2] = base[4];
                ah[i][3] = base[8*SROW + 4];
                const float* base2 = Alo + (wm + i*16 + g)*SROW + kk + t4;
                al[i][0] = base2[0];
                al[i][1] = base2[8*SROW];
                al[i][2] = base2[4];
                al[i][3] = base2[8*SROW + 4];
            }
            float bh[4][2], bl[4][2];
            #pragma unroll
            for (int j = 0; j < 4; j++) {
                const float* bb = Bhi + (wn + j*8 + g)*SROW + kk + t4;
                bh[j][0] = bb[0]; bh[j][1] = bb[4];
                const float* bb2 = Blo + (wn + j*8 + g)*SROW + kk + t4;
                bl[j][0] = bb2[0]; bl[j][1] = bb2[4];
            }
            #pragma unroll
            for (int i = 0; i < 4; i++)
                #pragma unroll
                for (int j = 0; j < 4; j++) {
                    mma8(d[i][j], ah[i], bh[j][0], bh[j][1]);
                    mma8(d[i][j], al[i], bh[j][0], bh[j][1]);
                    mma8(d[i][j], ah[i], bl[j][0], bl[j][1]);
                }
        }

        if (t + 1 < T) {
            STS((t + 1) & 1);
            if (t + 2 < T) LDG(t + 2);
        }
        __syncthreads();
    }

    float alpha = 1.f;
    if (slot >= 0) alpha = g_absmax[slot] * (1.f/127.f) + 1e-8f;
    int r = lane >> 2, c2 = (lane & 3) * 2;

    #pragma unroll
    for (int j = 0; j < 4; j++) {
        int cc = n0 + wn + j*8 + c2;
        float b0 = bias[cc], b1 = bias[cc + 1];
        #pragma unroll
        for (int i = 0; i < 4; i++) {
            int r0 = m0 + wm + i*16 + r;
            #pragma unroll
            for (int half = 0; half < 2; half++) {
                int rr = r0 + half*8;
                size_t idx = (size_t)rr*N + cc;
                float v0 = alpha * d[i][j][half*2 + 0] + b0;
                float v1 = alpha * d[i][j][half*2 + 1] + b1;
                if (EPI == 2) { v0 += e1[idx]; v1 += e1[idx + 1]; }
                float2 o; o.x = v0; o.y = v1;
                *(float2*)(C + idx) = o;
            }
        }
    }
}

// ================= bf16 x2 GEMM (quantized-code activations) =================
// A codes exact in bf16; B split bf16 hi + lo. mma.m16n8k16, KC=32 (2 kk-steps).
// Smem unit = b32 (bf16x2). Row stride 20 units (16 data + 4 pad), conflict-free.
#define SROWQ 20
#define TILEQ (128*SROWQ)   /* 2560 b32 units per tile */

template<int EPI>
__global__ void __launch_bounds__(256) mma_gemm_q(
    const float* __restrict__ A, const float* __restrict__ W,
    const float* __restrict__ bias, float* __restrict__ C,
    int M, int N, int K,
    const float* __restrict__ e1, const float* __restrict__ e2, int slot)
{
    extern __shared__ uint32_t smem_u[];

    int tid = threadIdx.x;
    int wid = tid >> 5, lane = tid & 31;
    int wm = (wid & 1) * 64;
    int wn = (wid >> 1) * 32;
    int m0 = blockIdx.y * 128, n0 = blockIdx.x * 128;
    int lrow = tid >> 3, lc4 = (tid & 7) * 4;   // 4-float chunks along K
    int g = lane >> 2, t4 = lane & 3;

    float d[4][4][4];
    #pragma unroll
    for (int i = 0; i < 4; i++)
        #pragma unroll
        for (int j = 0; j < 4; j++)
            #pragma unroll
            for (int q = 0; q < 4; q++) d[i][j][q] = 0.f;

    float4 av[4], wv[4];
    auto LDG = [&](int t){
        int k0 = t*KC + lc4;
        #pragma unroll
        for (int h = 0; h < 4; h++) {
            av[h] = *(const float4*)(A + (size_t)(m0 + lrow + h*32)*K + k0);
            wv[h] = *(const float4*)(W + (size_t)(n0 + lrow + h*32)*K + k0);
        }
    };
    auto STS = [&](int s){
        uint32_t* bufA  = smem_u + (size_t)s*3*TILEQ;
        uint32_t* bufBh = bufA + TILEQ;
        uint32_t* bufBl = bufBh + TILEQ;
        #pragma unroll
        for (int h = 0; h < 4; h++) {
            int u0 = (lrow + h*32)*SROWQ + (tid & 7)*2;
            // A codes: exact bf16
            bufA[u0]     = packbf(av[h].x, av[h].y);
            bufA[u0 + 1] = packbf(av[h].z, av[h].w);
            // B: hi + lo
            uint32_t h0 = packbf(wv[h].x, wv[h].y);
            uint32_t h1 = packbf(wv[h].z, wv[h].w);
            float e0 = __uint_as_float(h0 << 16);
            float e1f = __uint_as_float(h0 & 0xffff0000u);
            float e2f = __uint_as_float(h1 << 16);
            float e3 = __uint_as_float(h1 & 0xffff0000u);
            bufBh[u0]     = h0;
            bufBh[u0 + 1] = h1;
            bufBl[u0]     = packbf(wv[h].x - e0, wv[h].y - e1f);
            bufBl[u0 + 1] = packbf(wv[h].z - e2f, wv[h].w - e3);
        }
    };

    const int T = K / KC;
    LDG(0); STS(0);
    if (T > 1) LDG(1);
    __syncthreads();

    for (int t = 0; t < T; t++) {
        const uint32_t* buf = smem_u + (size_t)(t & 1)*3*TILEQ;
        const uint32_t* Au  = buf;
        const uint32_t* Bh  = buf + TILEQ;
        const uint32_t* Bl  = buf + 2*TILEQ;

        #pragma unroll
        for (int ks = 0; ks < 2; ks++) {           // two k16 steps per KC=32
            int ku = ks*8;                          // unit offset
            uint32_t a[4][4];
            #pragma unroll
            for (int i = 0; i < 4; i++) {
                const uint32_t* base = Au + (wm + i*16 + g)*SROWQ + ku + t4;
                a[i][0] = base[0];
                a[i][1] = base[8*SROWQ];
                a[i][2] = base[4];
                a[i][3] = base[8*SROWQ + 4];
            }
            uint32_t bh[4][2], bl[4][2];
            #pragma unroll
            for (int j = 0; j < 4; j++) {
                const uint32_t* bb = Bh + (wn + j*8 + g)*SROWQ + ku + t4;
                bh[j][0] = bb[0]; bh[j][1] = bb[4];
                const uint32_t* bb2 = Bl + (wn + j*8 + g)*SROWQ + ku + t4;
                bl[j][0] = bb2[0]; bl[j][1] = bb2[4];
            }
            #pragma unroll
            for (int i = 0; i < 4; i++)
                #pragma unroll
                for (int j = 0; j < 4; j++) {
                    mma16(d[i][j], a[i], bh[j][0], bh[j][1]);
                    mma16(d[i][j], a[i], bl[j][0], bl[j][1]);
                }
        }

        if (t + 1 < T) {
            STS((t + 1) & 1);
            if (t + 2 < T) LDG(t + 2);
        }
        __syncthreads();
    }

    float alpha = g_absmax[slot] * (1.f/127.f) + 1e-8f;
    int r = lane >> 2, c2 = (lane & 3) * 2;

    #pragma unroll
    for (int j = 0; j < 4; j++) {
        int cc = n0 + wn + j*8 + c2;
        float b0 = bias[cc], b1 = bias[cc + 1];
        float dn0 = 0.f, dn1 = 0.f;
        if (EPI == 1) { dn0 = expf(e2[cc]); dn1 = expf(e2[cc + 1]); }
        #pragma unroll
        for (int i = 0; i < 4; i++) {
            int r0 = m0 + wm + i*16 + r;
            #pragma unroll
            for (int half = 0; half < 2; half++) {
                int rr = r0 + half*8;
                size_t idx = (size_t)rr*N + cc;
                float v0 = alpha * d[i][j][half*2 + 0] + b0;
                float v1 = alpha * d[i][j][half*2 + 1] + b1;
                if (EPI == 1) {
                    v0 = tanhf(v0 + dn0 * e1[idx]);
                    v1 = tanhf(v1 + dn1 * e1[idx + 1]);
                } else if (EPI == 2) {
                    v0 += e1[idx];
                    v1 += e1[idx + 1];
                }
                float2 o; o.x = v0; o.y = v1;
                *(float2*)(C + idx) = o;
            }
        }
    }
}

// ================= MMA flash attention (tf32 x3) =================
#define SKA 68
#define SVA 72
#define SPA 68
#define OFF_KLO 4352
#define OFF_VHI 8704
#define OFF_VLO 13312
#define OFF_PHI 17920
#define OFF_PLO 26624
#define ATTN_SMEM (35328*4)

__global__ void __launch_bounds__(256) attn_mma(
    const float* __restrict__ qkv, float* __restrict__ out)
{
    extern __shared__ float smem_f[];
    float* Khi = smem_f;
    float* Klo = smem_f + OFF_KLO;
    float* Vhi = smem_f + OFF_VHI;
    float* Vlo = smem_f + OFF_VLO;
    float* Phi = smem_f + OFF_PHI;
    float* Plo = smem_f + OFF_PLO;

    int tid = threadIdx.x, w = tid >> 5, lane = tid & 31;
    int g = lane >> 2, t = lane & 3;
    int q0 = blockIdx.x * 128, h = blockIdx.y, b = blockIdx.z;
    const float* base = qkv + (size_t)b*SQ*3072 + h*64;

    for (int i = tid; i < 2048; i += 256) {
        int row = i >> 4, c4 = (i & 15) * 4;
        float4 v = *(const float4*)(base + (size_t)(q0 + row)*3072 + c4);
        v.x *= 0.125f; v.y *= 0.125f; v.z *= 0.125f; v.w *= 0.125f;
        *(float4*)(Phi + row*SPA + c4) = v;
    }
    __syncthreads();

    float qh[8][4], ql[8][4];
    {
        const float* Qw = Phi + (w*16)*SPA;
        #pragma unroll
        for (int kk = 0; kk < 8; kk++) {
            #pragma unroll
            for (int q = 0; q < 4; q++) {
                int row = (q & 1) ? (g + 8) : g;
                int col = kk*8 + t + ((q & 2) ? 4 : 0);
                float x = Qw[row*SPA + col];
                qh[kk][q] = tf32h(x);
                ql[kk][q] = tf32h(x - qh[kk][q]);
            }
        }
    }

    float o[8][4];
    #pragma unroll
    for (int j = 0; j < 8; j++)
        #pragma unroll
        for (int q = 0; q < 4; q++) o[j][q] = 0.f;
    float m0 = -1e30f, m1 = -1e30f, l0 = 0.f, l1 = 0.f;

    for (int kt = 0; kt < SQ/64; kt++) {
        __syncthreads();
        for (int i = tid; i < 1024; i += 256) {
            int row = i >> 4, c4 = (i & 15) * 4;
            const float* gp = base + (size_t)(kt*64 + row)*3072 + 1024 + c4;
            float4 kv = *(const float4*)gp;
            float4 vv = *(const float4*)(gp + 1024);
            float4 khv, klv, vhv, vlv;
            khv.x = tf32h(kv.x); khv.y = tf32h(kv.y); khv.z = tf32h(kv.z); khv.w = tf32h(kv.w);
            klv.x = tf32h(kv.x - khv.x); klv.y = tf32h(kv.y - khv.y);
            klv.z = tf32h(kv.z - khv.z); klv.w = tf32h(kv.w - khv.w);
            vhv.x = tf32h(vv.x); vhv.y = tf32h(vv.y); vhv.z = tf32h(vv.z); vhv.w = tf32h(vv.w);
            vlv.x = tf32h(vv.x - vhv.x); vlv.y = tf32h(vv.y - vhv.y);
            vlv.z = tf32h(vv.z - vhv.z); vlv.w = tf32h(vv.w - vhv.w);
            *(float4*)(Khi + row*SKA + c4) = khv;
            *(float4*)(Klo + row*SKA + c4) = klv;
            *(float4*)(Vhi + row*SVA + c4) = vhv;
            *(float4*)(Vlo + row*SVA + c4) = vlv;
        }
        __syncthreads();

        float s[8][4];
        #pragma unroll
        for (int j = 0; j < 8; j++)
            #pragma unroll
            for (int q = 0; q < 4; q++) s[j][q] = 0.f;

        #pragma unroll
        for (int j = 0; j < 8; j++) {
            #pragma unroll
            for (int kk = 0; kk < 8; kk++) {
                const float* kh = Khi + (j*8 + g)*SKA + kk*8 + t;
                const float* kl = Klo + (j*8 + g)*SKA + kk*8 + t;
                float bh0 = kh[0], bh1 = kh[4];
                float bl0 = kl[0], bl1 = kl[4];
                mma8(s[j], qh[kk], bh0, bh1);
                mma8(s[j], ql[kk], bh0, bh1);
                mma8(s[j], qh[kk], bl0, bl1);
            }
        }

        float mt0 = -1e30f, mt1 = -1e30f;
        #pragma unroll
        for (int j = 0; j < 8; j++) {
            mt0 = fmaxf(mt0, fmaxf(s[j][0], s[j][1]));
            mt1 = fmaxf(mt1, fmaxf(s[j][2], s[j][3]));
        }
        mt0 = fmaxf(mt0, __shfl_xor_sync(0xffffffffu, mt0, 1));
        mt0 = fmaxf(mt0, __shfl_xor_sync(0xffffffffu, mt0, 2));
        mt1 = fmaxf(mt1, __shfl_xor_sync(0xffffffffu, mt1, 1));
        mt1 = fmaxf(mt1, __shfl_xor_sync(0xffffffffu, mt1, 2));
        float m0n = fmaxf(m0, mt0), m1n = fmaxf(m1, mt1);
        float a0 = fexp(m0 - m0n), a1 = fexp(m1 - m1n);

        float rs0 = 0.f, rs1 = 0.f;
        float* Pwh = Phi + (w*16)*SPA;
        float* Pwl = Plo + (w*16)*SPA;
        #pragma unroll
        for (int j = 0; j < 8; j++) {
            float p0 = fexp(s[j][0] - m0n), p1 = fexp(s[j][1] - m0n);
            float p2 = fexp(s[j][2] - m1n), p3 = fexp(s[j][3] - m1n);
            rs0 += p0 + p1; rs1 += p2 + p3;
            float h0 = tf32h(p0), h1 = tf32h(p1), h2 = tf32h(p2), h3 = tf32h(p3);
            int c0 = j*8 + 2*t;
            *(float2*)(Pwh + g*SPA + c0)       = make_float2(h0, h1);
            *(float2*)(Pwh + (g+8)*SPA + c0)   = make_float2(h2, h3);
            *(float2*)(Pwl + g*SPA + c0)       = make_float2(tf32h(p0 - h0), tf32h(p1 - h1));
            *(float2*)(Pwl + (g+8)*SPA + c0)   = make_float2(tf32h(p2 - h2), tf32h(p3 - h3));
        }
        rs0 += __shfl_xor_sync(0xffffffffu, rs0, 1);
        rs0 += __shfl_xor_sync(0xffffffffu, rs0, 2);
        rs1 += __shfl_xor_sync(0xffffffffu, rs1, 1);
        rs1 += __shfl_xor_sync(0xffffffffu, rs1, 2);
        l0 = l0*a0 + rs0;
        l1 = l1*a1 + rs1;
        m0 = m0n; m1 = m1n;
        #pragma unroll
        for (int j = 0; j < 8; j++) {
            o[j][0] *= a0; o[j][1] *= a0; o[j][2] *= a1; o[j][3] *= a1;
        }
        __syncwarp();

        #pragma unroll
        for (int kk = 0; kk < 8; kk++) {
            float ah[4], al[4];
            const float* ph = Phi + (w*16 + g)*SPA + kk*8 + t;
            const float* pl = Plo + (w*16 + g)*SPA + kk*8 + t;
            ah[0] = ph[0]; ah[1] = ph[8*SPA]; ah[2] = ph[4]; ah[3] = ph[8*SPA + 4];
            al[0] = pl[0]; al[1] = pl[8*SPA]; al[2] = pl[4]; al[3] = pl[8*SPA + 4];
            #pragma unroll
            for (int j = 0; j < 8; j++) {
                const float* vh = Vhi + (kk*8 + t)*SVA + j*8 + g;
                const float* vl = Vlo + (kk*8 + t)*SVA + j*8 + g;
                float bh0 = vh[0], bh1 = vh[4*SVA];
                float bl0 = vl[0], bl1 = vl[4*SVA];
                mma8(o[j], ah, bh0, bh1);
                mma8(o[j], al, bh0, bh1);
                mma8(o[j], ah, bl0, bl1);
            }
        }
    }

    float inv0 = 1.f / l0, inv1 = 1.f / l1;
    int row0 = q0 + w*16 + g;
    #pragma unroll
    for (int j = 0; j < 8; j++) {
        int col = h*64 + j*8 + 2*t;
        *(float2*)(out + (size_t)(b*SQ + row0)*DD + col) =
            make_float2(o[j][0]*inv0, o[j][1]*inv0);
        *(float2*)(out + (size_t)(b*SQ + row0 + 8)*DD + col) =
            make_float2(o[j][2]*inv1, o[j][3]*inv1);
    }
}

// ---------------- launch ----------------
extern "C" void kernel_launch(void* const* d_in, const int* in_sizes, int n_in,
                              void* d_out, int out_size)
{
    const float* x         = (const float*)d_in[0];
    const float* h_prev    = (const float*)d_in[1];
    const float* norm1_w   = (const float*)d_in[2];
    const float* norm2_w   = (const float*)d_in[3];
    const float* decay     = (const float*)d_in[4];
    const float* rec_W     = (const float*)d_in[5];
    const float* rec_b     = (const float*)d_in[6];
    const float* in_proj_w = (const float*)d_in[7];
    const float* in_proj_b = (const float*)d_in[8];
    const float* out_w     = (const float*)d_in[9];
    const float* out_b     = (const float*)d_in[10];
    const float* conv_w    = (const float*)d_in[11];
    const float* conv_b    = (const float*)d_in[12];
    const float* w1_W      = (const float*)d_in[13];
    const float* w1_b      = (const float*)d_in[14];
    const float* w2_W      = (const float*)d_in[15];
    const float* w2_b      = (const float*)d_in[16];
    const float* w3_W      = (const float*)d_in[17];
    const float* w3_b      = (const float*)d_in[18];

    float* out_x    = (float*)d_out;
    float* out_hrec = out_x + NELEM;

    float *nx, *nx2, *qkv, *attnpre, *hattn, *xbuf, *ff1, *ff2;
    cudaGetSymbolAddress((void**)&nx,      g_nx);
    cudaGetSymbolAddress((void**)&nx2,     g_nx2);
    cudaGetSymbolAddress((void**)&qkv,     g_qkv);
    cudaGetSymbolAddress((void**)&attnpre, g_attnpre);
    cudaGetSymbolAddress((void**)&hattn,   g_hattn);
    cudaGetSymbolAddress((void**)&xbuf,    g_xbuf);
    cudaGetSymbolAddress((void**)&ff1,     g_ff1);
    cudaGetSymbolAddress((void**)&ff2,     g_ff2);

    const int SM0 = 2*4*TILEF*4;    // tf32 kernel: 147456 B
    const int SMQ = 2*3*TILEQ*4;    // bf16 kernel: 61440 B
    cudaFuncSetAttribute(mma_gemm<0>,   cudaFuncAttributeMaxDynamicSharedMemorySize, SM0);
    cudaFuncSetAttribute(mma_gemm_q<0>, cudaFuncAttributeMaxDynamicSharedMemorySize, SMQ);
    cudaFuncSetAttribute(mma_gemm_q<1>, cudaFuncAttributeMaxDynamicSharedMemorySize, SMQ);
    cudaFuncSetAttribute(mma_gemm_q<2>, cudaFuncAttributeMaxDynamicSharedMemorySize, SMQ);
    cudaFuncSetAttribute(attn_mma, cudaFuncAttributeMaxDynamicSharedMemorySize, ATTN_SMEM);

    zero_absmax_kernel<<<1, 32>>>();
    rmsnorm_kernel<<<ROWS, 256>>>(x, norm1_w, nx, 0);
    quant_kernel<<<2048, 256>>>(nx, nx2, 0, NELEM/4);
    // qkv = nx @ in_proj_w^T + b   (tf32x3)
    mma_gemm<0><<<dim3(24, 64), 256, SM0>>>(nx, in_proj_w, in_proj_b, qkv,
                                            ROWS, 3072, 1024, nullptr, nullptr, -1);
    // h_rec = tanh(scale0*(codes @ rec_W^T) + rec_b + exp(decay)*h_prev)   (bf16)
    mma_gemm_q<1><<<dim3(8, 64), 256, SMQ>>>(nx2, rec_W, rec_b, out_hrec,
                                             ROWS, 1024, 1024, h_prev, decay, 0);
    // flash attention (tensor cores, tf32x3)
    attn_mma<<<dim3(16, 16, 4), 256, ATTN_SMEM>>>(qkv, attnpre);
    // out projection (tf32x3)
    mma_gemm<0><<<dim3(8, 64), 256, SM0>>>(attnpre, out_w, out_b, hattn,
                                           ROWS, 1024, 1024, nullptr, nullptr, -1);
    conv_combine_kernel<<<ROWS, 256>>>(x, out_hrec, hattn, nx, conv_w, conv_b, xbuf);
    rmsnorm_kernel<<<ROWS, 256>>>(xbuf, norm2_w, nx2, 1);
    quant_kernel<<<2048, 256>>>(nx2, nx2, 1, NELEM/4);
    // ff1/ff2 (bf16)
    mma_gemm_q<0><<<dim3(32, 64), 256, SMQ>>>(nx2, w1_W, w1_b, ff1,
                                              ROWS, 4096, 1024, nullptr, nullptr, 1);
    mma_gemm_q<0><<<dim3(32, 64), 256, SMQ>>>(nx2, w2_W, w2_b, ff2,
                                              ROWS, 4096, 1024, nullptr, nullptr, 1);
    gate_kernel<<<4096, 256>>>(ff1, ff2, (ROWS*4096)/4, 2);
    quant_kernel<<<4096, 256>>>(ff1, ff1, 2, (ROWS*4096)/4);
    // out_x = xbuf + scale2*(codes @ w3^T) + b3   (bf16)
    mma_gemm_q<2><<<dim3(8, 64), 256, SMQ>>>(ff1, w3_W, w3_b, out_x,
                                             ROWS, 1024, 4096, xbuf, nullptr, 2);
}

// round 8
// speedup vs baseline: 3.5946x; 1.1454x over previous
#include <cuda_runtime.h>
#include <cstdint>

#define DD 1024
#define NB 4
#define SQ 2048
#define ROWS (NB*SQ)            /* 8192 */
#define NELEM (ROWS*DD)         /* 8388608 */

// ---------------- scratch ----------------
__device__ float g_absmax[4];
__device__ float g_nx[NELEM];
__device__ float g_nx2[NELEM];
__device__ float g_qkv[ROWS*3*DD];
__device__ float g_attnpre[NELEM];
__device__ float g_hattn[NELEM];
__device__ float g_xbuf[NELEM];
__device__ float g_ff1[ROWS*4*DD];
__device__ float g_ff2[ROWS*4*DD];

// ---------------- helpers ----------------
__device__ __forceinline__ float tf32h(float x){
    uint32_t r; asm("cvt.rna.tf32.f32 %0, %1;" : "=r"(r) : "f"(x));
    return __uint_as_float(r);
}
__device__ __forceinline__ uint32_t packbf(float lo, float hi){
    uint32_t r; asm("cvt.rn.bf16x2.f32 %0, %1, %2;" : "=r"(r) : "f"(hi), "f"(lo));
    return r;
}
// fast exp: exp(x) = 2^(x*log2e), poly on [-0.5,0.5], rel err ~2e-6
__device__ __forceinline__ float fexp(float x){
    float y = x * 1.4426950408889634f;
    y = fminf(fmaxf(y, -120.f), 120.f);
    float r = rintf(y);
    float f = y - r;
    float p = 1.f + f*(0.6931471805599453f + f*(0.2402265069591007f +
              f*(0.05550410866482158f + f*(0.009618129107628477f +
              f*0.0013333558146428443f))));
    return __int_as_float(__float_as_int(p) + (((int)r) << 23));
}
__device__ __forceinline__ void mma8(float (&d)[4], const float* a, float b0, float b1){
    asm volatile("mma.sync.aligned.m16n8k8.row.col.f32.tf32.tf32.f32 "
        "{%0,%1,%2,%3},{%4,%5,%6,%7},{%8,%9},{%0,%1,%2,%3};"
        : "+f"(d[0]),"+f"(d[1]),"+f"(d[2]),"+f"(d[3])
        : "r"(__float_as_uint(a[0])),"r"(__float_as_uint(a[1])),
          "r"(__float_as_uint(a[2])),"r"(__float_as_uint(a[3])),
          "r"(__float_as_uint(b0)),"r"(__float_as_uint(b1)));
}
__device__ __forceinline__ void mma16(float (&d)[4], const uint32_t* a, uint32_t b0, uint32_t b1){
    asm volatile("mma.sync.aligned.m16n8k16.row.col.f32.bf16.bf16.f32 "
        "{%0,%1,%2,%3},{%4,%5,%6,%7},{%8,%9},{%0,%1,%2,%3};"
        : "+f"(d[0]),"+f"(d[1]),"+f"(d[2]),"+f"(d[3])
        : "r"(a[0]),"r"(a[1]),"r"(a[2]),"r"(a[3]),"r"(b0),"r"(b1));
}
// split fp32 pair into bf16x2 hi word + lo word
__device__ __forceinline__ void bfsplit(float x, float y, uint32_t& hi, uint32_t& lo){
    hi = packbf(x, y);
    float e0 = __uint_as_float(hi << 16);
    float e1 = __uint_as_float(hi & 0xffff0000u);
    lo = packbf(x - e0, y - e1);
}

// ---------------- small kernels ----------------
__global__ void zero_absmax_kernel() {
    if (threadIdx.x < 4) g_absmax[threadIdx.x] = 0.f;
}

__global__ void __launch_bounds__(256) rmsnorm_kernel(
    const float* __restrict__ x, const float* __restrict__ w,
    float* __restrict__ out, int slot)
{
    __shared__ float red[256];
    int tid = threadIdx.x;
    size_t row = blockIdx.x;
    float4 xv = ((const float4*)(x + row*DD))[tid];
    float ss = xv.x*xv.x + xv.y*xv.y + xv.z*xv.z + xv.w*xv.w;
    red[tid] = ss;
    __syncthreads();
    #pragma unroll
    for (int s = 128; s > 0; s >>= 1) {
        if (tid < s) red[tid] += red[tid + s];
        __syncthreads();
    }
    float rinv = rsqrtf(red[0] * (1.f/1024.f) + 1e-6f);
    __syncthreads();
    float4 wv = ((const float4*)w)[tid];
    float4 o;
    o.x = wv.x * (xv.x * rinv);
    o.y = wv.y * (xv.y * rinv);
    o.z = wv.z * (xv.z * rinv);
    o.w = wv.w * (xv.w * rinv);
    ((float4*)(out + row*DD))[tid] = o;
    float am = fmaxf(fmaxf(fabsf(o.x), fabsf(o.y)), fmaxf(fabsf(o.z), fabsf(o.w)));
    red[tid] = am;
    __syncthreads();
    #pragma unroll
    for (int s = 128; s > 0; s >>= 1) {
        if (tid < s) red[tid] = fmaxf(red[tid], red[tid + s]);
        __syncthreads();
    }
    if (tid == 0) atomicMax((int*)&g_absmax[slot], __float_as_int(red[0]));
}

__global__ void __launch_bounds__(256) quant_kernel(
    const float* __restrict__ in, float* __restrict__ out, int slot, int n4)
{
    float scale = g_absmax[slot] / 127.0f + 1e-8f;
    int stride = gridDim.x * blockDim.x;
    for (int i = blockIdx.x*blockDim.x + threadIdx.x; i < n4; i += stride) {
        float4 v = ((const float4*)in)[i];
        v.x = fminf(fmaxf(rintf(v.x / scale), -128.f), 127.f);
        v.y = fminf(fmaxf(rintf(v.y / scale), -128.f), 127.f);
        v.z = fminf(fmaxf(rintf(v.z / scale), -128.f), 127.f);
        v.w = fminf(fmaxf(rintf(v.w / scale), -128.f), 127.f);
        ((float4*)out)[i] = v;
    }
}

__global__ void __launch_bounds__(256) gate_kernel(
    float* __restrict__ a, const float* __restrict__ bsrc, int n4, int slot)
{
    __shared__ float red[256];
    float am = 0.f;
    int stride = gridDim.x * blockDim.x;
    for (int i = blockIdx.x*blockDim.x + threadIdx.x; i < n4; i += stride) {
        float4 u = ((const float4*)a)[i];
        float4 v = ((const float4*)bsrc)[i];
        float4 g;
        g.x = u.x / (1.f + fexp(-u.x)) * v.x;
        g.y = u.y / (1.f + fexp(-u.y)) * v.y;
        g.z = u.z / (1.f + fexp(-u.z)) * v.z;
        g.w = u.w / (1.f + fexp(-u.w)) * v.w;
        ((float4*)a)[i] = g;
        am = fmaxf(am, fmaxf(fmaxf(fabsf(g.x), fabsf(g.y)), fmaxf(fabsf(g.z), fabsf(g.w))));
    }
    red[threadIdx.x] = am;
    __syncthreads();
    #pragma unroll
    for (int s = 128; s > 0; s >>= 1) {
        if (threadIdx.x < s) red[threadIdx.x] = fmaxf(red[threadIdx.x], red[threadIdx.x + s]);
        __syncthreads();
    }
    if (threadIdx.x == 0) atomicMax((int*)&g_absmax[slot], __float_as_int(red[0]));
}

__global__ void __launch_bounds__(256) conv_combine_kernel(
    const float* __restrict__ x, const float* __restrict__ hrec,
    const float* __restrict__ hattn, const float* __restrict__ nx,
    const float* __restrict__ conv_w, const float* __restrict__ conv_b,
    float* __restrict__ xout)
{
    int bs = blockIdx.x;
    int b = bs >> 11;
    int s = bs & 2047;
    size_t rowbase = (size_t)bs * DD;
    for (int d = threadIdx.x; d < DD; d += 256) {
        float acc = conv_b[d];
        #pragma unroll
        for (int t = 0; t < 5; t++) {
            int ssi = s + t - 2;
            if (ssi >= 0 && ssi < SQ)
                acc = fmaf(nx[((size_t)b*SQ + ssi)*DD + d], conv_w[d*5 + t], acc);
        }
        size_t idx = rowbase + d;
        xout[idx] = x[idx] + hrec[idx] + hattn[idx] + acc;
    }
}

// ================= bf16 GEMMs =================
// Smem unit = b32 (bf16x2). Row stride 20 units (16 data + 4 pad), conflict-free.
#define KC 32
#define SROWQ 20
#define TILEQ (128*SROWQ)   /* 2560 b32 units per tile */

// SPLITA=1: A fp32 -> hi+lo (3 products, bf16x3).  SPLITA=0: A exact codes (2 products).
// EPI 0: v.  EPI 1: tanh(v + exp(e2[n])*e1[m,n]).  EPI 2: v + e1[m,n].
template<int SPLITA, int EPI>
__global__ void __launch_bounds__(256) mma_gemm_q(
    const float* __restrict__ A, const float* __restrict__ W,
    const float* __restrict__ bias, float* __restrict__ C,
    int M, int N, int K,
    const float* __restrict__ e1, const float* __restrict__ e2, int slot)
{
    extern __shared__ uint32_t smem_u[];
    const int NT = SPLITA ? 4 : 3;

    int tid = threadIdx.x;
    int wid = tid >> 5, lane = tid & 31;
    int wm = (wid & 1) * 64;
    int wn = (wid >> 1) * 32;
    int m0 = blockIdx.y * 128, n0 = blockIdx.x * 128;
    int lrow = tid >> 3, lc4 = (tid & 7) * 4;
    int g = lane >> 2, t4 = lane & 3;

    float d[4][4][4];
    #pragma unroll
    for (int i = 0; i < 4; i++)
        #pragma unroll
        for (int j = 0; j < 4; j++)
            #pragma unroll
            for (int q = 0; q < 4; q++) d[i][j][q] = 0.f;

    float4 av[4], wv[4];
    auto LDG = [&](int t){
        int k0 = t*KC + lc4;
        #pragma unroll
        for (int h = 0; h < 4; h++) {
            av[h] = *(const float4*)(A + (size_t)(m0 + lrow + h*32)*K + k0);
            wv[h] = *(const float4*)(W + (size_t)(n0 + lrow + h*32)*K + k0);
        }
    };
    auto STS = [&](int s){
        uint32_t* bufAh = smem_u + (size_t)s*NT*TILEQ;
        uint32_t* bufAl = bufAh + TILEQ;                  // SPLITA only
        uint32_t* bufBh = bufAh + (SPLITA ? 2 : 1)*TILEQ;
        uint32_t* bufBl = bufBh + TILEQ;
        #pragma unroll
        for (int h = 0; h < 4; h++) {
            int u0 = (lrow + h*32)*SROWQ + (tid & 7)*2;
            if (SPLITA) {
                uint32_t h0, l0, h1, l1;
                bfsplit(av[h].x, av[h].y, h0, l0);
                bfsplit(av[h].z, av[h].w, h1, l1);
                bufAh[u0] = h0; bufAh[u0 + 1] = h1;
                bufAl[u0] = l0; bufAl[u0 + 1] = l1;
            } else {
                bufAh[u0]     = packbf(av[h].x, av[h].y);
                bufAh[u0 + 1] = packbf(av[h].z, av[h].w);
            }
            uint32_t h0, l0, h1, l1;
            bfsplit(wv[h].x, wv[h].y, h0, l0);
            bfsplit(wv[h].z, wv[h].w, h1, l1);
            bufBh[u0] = h0; bufBh[u0 + 1] = h1;
            bufBl[u0] = l0; bufBl[u0 + 1] = l1;
        }
    };

    const int T = K / KC;
    LDG(0); STS(0);
    if (T > 1) LDG(1);
    __syncthreads();

    for (int t = 0; t < T; t++) {
        const uint32_t* buf = smem_u + (size_t)(t & 1)*NT*TILEQ;
        const uint32_t* Ah  = buf;
        const uint32_t* Al  = buf + TILEQ;
        const uint32_t* Bh  = buf + (SPLITA ? 2 : 1)*TILEQ;
        const uint32_t* Bl  = Bh + TILEQ;

        #pragma unroll
        for (int ks = 0; ks < 2; ks++) {
            int ku = ks*8;
            uint32_t ah[4][4], al[4][4];
            #pragma unroll
            for (int i = 0; i < 4; i++) {
                const uint32_t* base = Ah + (wm + i*16 + g)*SROWQ + ku + t4;
                ah[i][0] = base[0];
                ah[i][1] = base[8*SROWQ];
                ah[i][2] = base[4];
                ah[i][3] = base[8*SROWQ + 4];
                if (SPLITA) {
                    const uint32_t* b2 = Al + (wm + i*16 + g)*SROWQ + ku + t4;
                    al[i][0] = b2[0];
                    al[i][1] = b2[8*SROWQ];
                    al[i][2] = b2[4];
                    al[i][3] = b2[8*SROWQ + 4];
                }
            }
            uint32_t bh[4][2], bl[4][2];
            #pragma unroll
            for (int j = 0; j < 4; j++) {
                const uint32_t* bb = Bh + (wn + j*8 + g)*SROWQ + ku + t4;
                bh[j][0] = bb[0]; bh[j][1] = bb[4];
                const uint32_t* bb2 = Bl + (wn + j*8 + g)*SROWQ + ku + t4;
                bl[j][0] = bb2[0]; bl[j][1] = bb2[4];
            }
            #pragma unroll
            for (int i = 0; i < 4; i++)
                #pragma unroll
                for (int j = 0; j < 4; j++) {
                    mma16(d[i][j], ah[i], bh[j][0], bh[j][1]);
                    if (SPLITA) mma16(d[i][j], al[i], bh[j][0], bh[j][1]);
                    mma16(d[i][j], ah[i], bl[j][0], bl[j][1]);
                }
        }

        if (t + 1 < T) {
            STS((t + 1) & 1);
            if (t + 2 < T) LDG(t + 2);
        }
        __syncthreads();
    }

    float alpha = 1.f;
    if (slot >= 0) alpha = g_absmax[slot] * (1.f/127.f) + 1e-8f;
    int r = lane >> 2, c2 = (lane & 3) * 2;

    #pragma unroll
    for (int j = 0; j < 4; j++) {
        int cc = n0 + wn + j*8 + c2;
        float b0 = bias[cc], b1 = bias[cc + 1];
        float dn0 = 0.f, dn1 = 0.f;
        if (EPI == 1) { dn0 = expf(e2[cc]); dn1 = expf(e2[cc + 1]); }
        #pragma unroll
        for (int i = 0; i < 4; i++) {
            int r0 = m0 + wm + i*16 + r;
            #pragma unroll
            for (int half = 0; half < 2; half++) {
                int rr = r0 + half*8;
                size_t idx = (size_t)rr*N + cc;
                float v0 = alpha * d[i][j][half*2 + 0] + b0;
                float v1 = alpha * d[i][j][half*2 + 1] + b1;
                if (EPI == 1) {
                    v0 = tanhf(v0 + dn0 * e1[idx]);
                    v1 = tanhf(v1 + dn1 * e1[idx + 1]);
                } else if (EPI == 2) {
                    v0 += e1[idx];
                    v1 += e1[idx + 1];
                }
                float2 o; o.x = v0; o.y = v1;
                *(float2*)(C + idx) = o;
            }
        }
    }
}

// ================= MMA flash attention (QK bf16x3, PV tf32x3) =================
// K bf16x2 hi/lo: 64 rows x 32 units, stride 36 -> 2304 u32 each
// V fp32 tf32 hi/lo: 64 x 72 -> 4608 each
// P fp32 hi/lo (also Q staging): 128 x 68 -> 8704 each
#define SKB 36
#define SVA 72
#define SPA 68
#define OFF_KBL 2304
#define OFF_VHI 4608
#define OFF_VLO 9216
#define OFF_PHI 13824
#define OFF_PLO 22528
#define ATTN_SMEM (31232*4)

__global__ void __launch_bounds__(256) attn_mma(
    const float* __restrict__ qkv, float* __restrict__ out)
{
    extern __shared__ float smem_f[];
    uint32_t* Kbh = (uint32_t*)smem_f;
    uint32_t* Kbl = (uint32_t*)smem_f + OFF_KBL;
    float* Vhi = smem_f + OFF_VHI;
    float* Vlo = smem_f + OFF_VLO;
    float* Phi = smem_f + OFF_PHI;
    float* Plo = smem_f + OFF_PLO;

    int tid = threadIdx.x, w = tid >> 5, lane = tid & 31;
    int g = lane >> 2, t = lane & 3;
    int q0 = blockIdx.x * 128, h = blockIdx.y, b = blockIdx.z;
    const float* base = qkv + (size_t)b*SQ*3072 + h*64;

    // stage Q (scaled) in Phi, then extract bf16 hi/lo fragments
    for (int i = tid; i < 2048; i += 256) {
        int row = i >> 4, c4 = (i & 15) * 4;
        float4 v = *(const float4*)(base + (size_t)(q0 + row)*3072 + c4);
        v.x *= 0.125f; v.y *= 0.125f; v.z *= 0.125f; v.w *= 0.125f;
        *(float4*)(Phi + row*SPA + c4) = v;
    }
    __syncthreads();

    uint32_t qh[4][4], ql[4][4];
    {
        const float* Qw = Phi + (w*16)*SPA;
        #pragma unroll
        for (int ks = 0; ks < 4; ks++) {
            #pragma unroll
            for (int q = 0; q < 4; q++) {
                int row = (q & 1) ? (g + 8) : g;
                int ucol = ks*8 + t + ((q & 2) ? 4 : 0);
                float2 v = *(const float2*)(Qw + row*SPA + 2*ucol);
                bfsplit(v.x, v.y, qh[ks][q], ql[ks][q]);
            }
        }
    }

    float o[8][4];
    #pragma unroll
    for (int j = 0; j < 8; j++)
        #pragma unroll
        for (int q = 0; q < 4; q++) o[j][q] = 0.f;
    float m0 = -1e30f, m1 = -1e30f, l0 = 0.f, l1 = 0.f;

    for (int kt = 0; kt < SQ/64; kt++) {
        __syncthreads();
        for (int i = tid; i < 1024; i += 256) {
            int row = i >> 4, c4 = (i & 15) * 4;
            const float* gp = base + (size_t)(kt*64 + row)*3072 + 1024 + c4;
            float4 kv = *(const float4*)gp;
            float4 vv = *(const float4*)(gp + 1024);
            // K -> bf16 hi/lo packed pairs
            uint32_t h0, lo0, h1, lo1;
            bfsplit(kv.x, kv.y, h0, lo0);
            bfsplit(kv.z, kv.w, h1, lo1);
            int u = row*SKB + (i & 15)*2;
            Kbh[u] = h0; Kbh[u + 1] = h1;
            Kbl[u] = lo0; Kbl[u + 1] = lo1;
            // V -> tf32 hi/lo fp32
            float4 vhv, vlv;
            vhv.x = tf32h(vv.x); vhv.y = tf32h(vv.y); vhv.z = tf32h(vv.z); vhv.w = tf32h(vv.w);
            vlv.x = tf32h(vv.x - vhv.x); vlv.y = tf32h(vv.y - vhv.y);
            vlv.z = tf32h(vv.z - vhv.z); vlv.w = tf32h(vv.w - vhv.w);
            *(float4*)(Vhi + row*SVA + c4) = vhv;
            *(float4*)(Vlo + row*SVA + c4) = vlv;
        }
        __syncthreads();

        // ---- S = Q K^T  (bf16x3) ----
        float s[8][4];
        #pragma unroll
        for (int j = 0; j < 8; j++)
            #pragma unroll
            for (int q = 0; q < 4; q++) s[j][q] = 0.f;

        #pragma unroll
        for (int j = 0; j < 8; j++) {
            #pragma unroll
            for (int ks = 0; ks < 4; ks++) {
                const uint32_t* kb  = Kbh + (j*8 + g)*SKB + ks*8 + t;
                const uint32_t* kb2 = Kbl + (j*8 + g)*SKB + ks*8 + t;
                uint32_t bh0 = kb[0],  bh1 = kb[4];
                uint32_t bl0 = kb2[0], bl1 = kb2[4];
                mma16(s[j], qh[ks], bh0, bh1);
                mma16(s[j], ql[ks], bh0, bh1);
                mma16(s[j], qh[ks], bl0, bl1);
            }
        }

        // ---- online softmax ----
        float mt0 = -1e30f, mt1 = -1e30f;
        #pragma unroll
        for (int j = 0; j < 8; j++) {
            mt0 = fmaxf(mt0, fmaxf(s[j][0], s[j][1]));
            mt1 = fmaxf(mt1, fmaxf(s[j][2], s[j][3]));
        }
        mt0 = fmaxf(mt0, __shfl_xor_sync(0xffffffffu, mt0, 1));
        mt0 = fmaxf(mt0, __shfl_xor_sync(0xffffffffu, mt0, 2));
        mt1 = fmaxf(mt1, __shfl_xor_sync(0xffffffffu, mt1, 1));
        mt1 = fmaxf(mt1, __shfl_xor_sync(0xffffffffu, mt1, 2));
        float m0n = fmaxf(m0, mt0), m1n = fmaxf(m1, mt1);
        float a0 = fexp(m0 - m0n), a1 = fexp(m1 - m1n);

        float rs0 = 0.f, rs1 = 0.f;
        float* Pwh = Phi + (w*16)*SPA;
        float* Pwl = Plo + (w*16)*SPA;
        #pragma unroll
        for (int j = 0; j < 8; j++) {
            float p0 = fexp(s[j][0] - m0n), p1 = fexp(s[j][1] - m0n);
            float p2 = fexp(s[j][2] - m1n), p3 = fexp(s[j][3] - m1n);
            rs0 += p0 + p1; rs1 += p2 + p3;
            float h0 = tf32h(p0), h1 = tf32h(p1), h2 = tf32h(p2), h3 = tf32h(p3);
            int c0 = j*8 + 2*t;
            *(float2*)(Pwh + g*SPA + c0)       = make_float2(h0, h1);
            *(float2*)(Pwh + (g+8)*SPA + c0)   = make_float2(h2, h3);
            *(float2*)(Pwl + g*SPA + c0)       = make_float2(tf32h(p0 - h0), tf32h(p1 - h1));
            *(float2*)(Pwl + (g+8)*SPA + c0)   = make_float2(tf32h(p2 - h2), tf32h(p3 - h3));
        }
        rs0 += __shfl_xor_sync(0xffffffffu, rs0, 1);
        rs0 += __shfl_xor_sync(0xffffffffu, rs0, 2);
        rs1 += __shfl_xor_sync(0xffffffffu, rs1, 1);
        rs1 += __shfl_xor_sync(0xffffffffu, rs1, 2);
        l0 = l0*a0 + rs0;
        l1 = l1*a1 + rs1;
        m0 = m0n; m1 = m1n;
        #pragma unroll
        for (int j = 0; j < 8; j++) {
            o[j][0] *= a0; o[j][1] *= a0; o[j][2] *= a1; o[j][3] *= a1;
        }
        __syncwarp();

        // ---- O += P V  (tf32x3) ----
        #pragma unroll
        for (int kk = 0; kk < 8; kk++) {
            float ah[4], al[4];
            const float* ph = Phi + (w*16 + g)*SPA + kk*8 + t;
            const float* pl = Plo + (w*16 + g)*SPA + kk*8 + t;
            ah[0] = ph[0]; ah[1] = ph[8*SPA]; ah[2] = ph[4]; ah[3] = ph[8*SPA + 4];
            al[0] = pl[0]; al[1] = pl[8*SPA]; al[2] = pl[4]; al[3] = pl[8*SPA + 4];
            #pragma unroll
            for (int j = 0; j < 8; j++) {
                const float* vh = Vhi + (kk*8 + t)*SVA + j*8 + g;
                const float* vl = Vlo + (kk*8 + t)*SVA + j*8 + g;
                float bh0 = vh[0], bh1 = vh[4*SVA];
                float bl0 = vl[0], bl1 = vl[4*SVA];
                mma8(o[j], ah, bh0, bh1);
                mma8(o[j], al, bh0, bh1);
                mma8(o[j], ah, bl0, bl1);
            }
        }
    }

    float inv0 = 1.f / l0, inv1 = 1.f / l1;
    int row0 = q0 + w*16 + g;
    #pragma unroll
    for (int j = 0; j < 8; j++) {
        int col = h*64 + j*8 + 2*t;
        *(float2*)(out + (size_t)(b*SQ + row0)*DD + col) =
            make_float2(o[j][0]*inv0, o[j][1]*inv0);
        *(float2*)(out + (size_t)(b*SQ + row0 + 8)*DD + col) =
            make_float2(o[j][2]*inv1, o[j][3]*inv1);
    }
}

// ---------------- launch ----------------
extern "C" void kernel_launch(void* const* d_in, const int* in_sizes, int n_in,
                              void* d_out, int out_size)
{
    const float* x         = (const float*)d_in[0];
    const float* h_prev    = (const float*)d_in[1];
    const float* norm1_w   = (const float*)d_in[2];
    const float* norm2_w   = (const float*)d_in[3];
    const float* decay     = (const float*)d_in[4];
    const float* rec_W     = (const float*)d_in[5];
    const float* rec_b     = (const float*)d_in[6];
    const float* in_proj_w = (const float*)d_in[7];
    const float* in_proj_b = (const float*)d_in[8];
    const float* out_w     = (const float*)d_in[9];
    const float* out_b     = (const float*)d_in[10];
    const float* conv_w    = (const float*)d_in[11];
    const float* conv_b    = (const float*)d_in[12];
    const float* w1_W      = (const float*)d_in[13];
    const float* w1_b      = (const float*)d_in[14];
    const float* w2_W      = (const float*)d_in[15];
    const float* w2_b      = (const float*)d_in[16];
    const float* w3_W      = (const float*)d_in[17];
    const float* w3_b      = (const float*)d_in[18];

    float* out_x    = (float*)d_out;
    float* out_hrec = out_x + NELEM;

    float *nx, *nx2, *qkv, *attnpre, *hattn, *xbuf, *ff1, *ff2;
    cudaGetSymbolAddress((void**)&nx,      g_nx);
    cudaGetSymbolAddress((void**)&nx2,     g_nx2);
    cudaGetSymbolAddress((void**)&qkv,     g_qkv);
    cudaGetSymbolAddress((void**)&attnpre, g_attnpre);
    cudaGetSymbolAddress((void**)&hattn,   g_hattn);
    cudaGetSymbolAddress((void**)&xbuf,    g_xbuf);
    cudaGetSymbolAddress((void**)&ff1,     g_ff1);
    cudaGetSymbolAddress((void**)&ff2,     g_ff2);

    const int SMB3 = 2*4*TILEQ*4;   // SPLITA=1: 81920 B
    const int SMQ  = 2*3*TILEQ*4;   // SPLITA=0: 61440 B
    cudaFuncSetAttribute(mma_gemm_q<1,0>, cudaFuncAttributeMaxDynamicSharedMemorySize, SMB3);
    cudaFuncSetAttribute(mma_gemm_q<0,0>, cudaFuncAttributeMaxDynamicSharedMemorySize, SMQ);
    cudaFuncSetAttribute(mma_gemm_q<0,1>, cudaFuncAttributeMaxDynamicSharedMemorySize, SMQ);
    cudaFuncSetAttribute(mma_gemm_q<0,2>, cudaFuncAttributeMaxDynamicSharedMemorySize, SMQ);
    cudaFuncSetAttribute(attn_mma, cudaFuncAttributeMaxDynamicSharedMemorySize, ATTN_SMEM);

    zero_absmax_kernel<<<1, 32>>>();
    rmsnorm_kernel<<<ROWS, 256>>>(x, norm1_w, nx, 0);
    quant_kernel<<<2048, 256>>>(nx, nx2, 0, NELEM/4);
    // qkv = nx @ in_proj_w^T + b   (bf16x3)
    mma_gemm_q<1,0><<<dim3(24, 64), 256, SMB3>>>(nx, in_proj_w, in_proj_b, qkv,
                                                 ROWS, 3072, 1024, nullptr, nullptr, -1);
    // h_rec = tanh(scale0*(codes @ rec_W^T) + rec_b + exp(decay)*h_prev)   (bf16x2)
    mma_gemm_q<0,1><<<dim3(8, 64), 256, SMQ>>>(nx2, rec_W, rec_b, out_hrec,
                                               ROWS, 1024, 1024, h_prev, decay, 0);
    // flash attention
    attn_mma<<<dim3(16, 16, 4), 256, ATTN_SMEM>>>(qkv, attnpre);
    // out projection (bf16x3)
    mma_gemm_q<1,0><<<dim3(8, 64), 256, SMB3>>>(attnpre, out_w, out_b, hattn,
                                                ROWS, 1024, 1024, nullptr, nullptr, -1);
    conv_combine_kernel<<<ROWS, 256>>>(x, out_hrec, hattn, nx, conv_w, conv_b, xbuf);
    rmsnorm_kernel<<<ROWS, 256>>>(xbuf, norm2_w, nx2, 1);
    quant_kernel<<<2048, 256>>>(nx2, nx2, 1, NELEM/4);
    // ff1/ff2 (bf16x2)
    mma_gemm_q<0,0><<<dim3(32, 64), 256, SMQ>>>(nx2, w1_W, w1_b, ff1,
                                                ROWS, 4096, 1024, nullptr, nullptr, 1);
    mma_gemm_q<0,0><<<dim3(32, 64), 256, SMQ>>>(nx2, w2_W, w2_b, ff2,
                                                ROWS, 4096, 1024, nullptr, nullptr, 1);
    gate_kernel<<<4096, 256>>>(ff1, ff2, (ROWS*4096)/4, 2);
    quant_kernel<<<4096, 256>>>(ff1, ff1, 2, (ROWS*4096)/4);
    // out_x = xbuf + scale2*(codes @ w3^T) + b3   (bf16x2)
    mma_gemm_q<0,2><<<dim3(8, 64), 256, SMQ>>>(ff1, w3_W, w3_b, out_x,
                                               ROWS, 1024, 4096, xbuf, nullptr, 2);
}